// round 15
// baseline (speedup 1.0000x reference)
#include <cuda_runtime.h>
#include <math.h>

#define NRES 10000
#define KNN 30
#define HDIM 32
#define EFD 32
#define NEDGE (NRES*KNN)

// ---------------- device scratch ----------------
__device__ float g_h0[2][NRES*HDIM];
__device__ float g_h1[2][NRES*3*HDIM];
__device__ float g_ef[NEDGE*EFD];
__device__ int   g_src[NEDGE];
__device__ float4 g_xca4[NRES];
__device__ int   g_bstart[8];
__device__ int   g_bend[8];
// double-buffered by layer parity (writer = phase1 epilogue, reader = next phase1)
__device__ float g_hsS[2][NRES*HDIM];
__device__ float g_hdS[2][NRES*HDIM];
__device__ float g_hvS[2][3*NRES*HDIM];     // plane-major within slot
// single-buffered (produced by phase1(l), consumed by phase2(l) only)
__device__ float g_ps2[2][NRES*HDIM];       // plane = hidden half
__device__ float g_pd2[2][NRES*HDIM];

__constant__ int c_aa[87] = {
  0,
  1,1,1,1,1,1,1, 2,2,2,2, 3,3,3,3, 4,4, 5,5,5,5,5, 6,6,6,6,6,
  8,8,8,8,8,8, 9,9,9,9, 10,10,10,10, 11,11,11,11,11, 12,12,12,12,
  13,13,13,13,13,13,13, 14,14,14, 15,15, 16,16,16,
  17,17,17,17,17,17,17,17,17,17, 18,18,18,18,18,18,18,18, 19,19,19
};
__constant__ int c_off[87] = {
  0,
  0,1,2,3,4,5,6, 0,1,2,3, 0,1,2,3, 0,1, 0,1,2,3,4, 0,1,2,3,4,
  0,1,2,3,4,5, 0,1,2,3, 0,1,2,3, 0,1,2,3,4, 0,1,2,3,
  0,1,2,3,4,5,6, 0,1,2, 0,1, 0,1,2,
  0,1,2,3,4,5,6,7,8,9, 0,1,2,3,4,5,6,7, 0,1,2
};

__device__ __forceinline__ float fin0(float v){ return isfinite(v) ? v : 0.f; }

// ---------------- batch ranges ----------------
__global__ void init_ranges_kernel(){
  int t = threadIdx.x;
  if (t < 8){ g_bstart[t] = NRES; g_bend[t] = 0; }
}
__global__ void batch_range_kernel(const int* __restrict__ bid){
  int i = blockIdx.x*blockDim.x + threadIdx.x;
  if (i >= NRES) return;
  int b = bid[i];
  atomicMin(&g_bstart[b], i);
  atomicMax(&g_bend[b], i+1);
}

// ---------------- node features + embeddings + layer-0 precompute (slot 0) ----------------
__global__ __launch_bounds__(256) void node_embed_kernel(
    const float* __restrict__ bb, const float* __restrict__ lat,
    const float* __restrict__ Wemb0, const float* __restrict__ Wemb1,
    const float* __restrict__ Wss0, const float* __restrict__ Wds0,
    const float* __restrict__ Wvs0)
{
  int lane = threadIdx.x & 31;
  int i = blockIdx.x*8 + (threadIdx.x >> 5);
  if (i >= NRES) return;

  float ca0 = bb[i*12+3], ca1 = bb[i*12+4], ca2 = bb[i*12+5];
  if (lane == 0){
    g_xca4[i] = make_float4(ca0, ca1, ca2, ca0*ca0 + ca1*ca1 + ca2*ca2);
  }

  float Dv[3];
  #pragma unroll
  for (int t3 = 0; t3 < 3; t3++){
    int t = 3*i + t3;
    float D = 0.f;
    if (t >= 1 && t <= 3*NRES - 3){
      int d0 = t - 1;
      float x[4][3];
      #pragma unroll
      for (int q = 0; q < 4; q++){
        int m = d0 + q; int r = m/3; int am = m - r*3;
        x[q][0] = bb[r*12 + am*3 + 0];
        x[q][1] = bb[r*12 + am*3 + 1];
        x[q][2] = bb[r*12 + am*3 + 2];
      }
      float u2[3], u1[3], u0[3];
      #pragma unroll
      for (int c = 0; c < 3; c++){ u2[c]=x[1][c]-x[0][c]; u1[c]=x[2][c]-x[1][c]; u0[c]=x[3][c]-x[2][c]; }
      float n2n = sqrtf(u2[0]*u2[0]+u2[1]*u2[1]+u2[2]*u2[2]) + 1e-8f;
      float n1n = sqrtf(u1[0]*u1[0]+u1[1]*u1[1]+u1[2]*u1[2]) + 1e-8f;
      float n0n = sqrtf(u0[0]*u0[0]+u0[1]*u0[1]+u0[2]*u0[2]) + 1e-8f;
      #pragma unroll
      for (int c = 0; c < 3; c++){ u2[c]/=n2n; u1[c]/=n1n; u0[c]/=n0n; }
      float c21[3] = { u2[1]*u1[2]-u2[2]*u1[1], u2[2]*u1[0]-u2[0]*u1[2], u2[0]*u1[1]-u2[1]*u1[0] };
      float c10[3] = { u1[1]*u0[2]-u1[2]*u0[1], u1[2]*u0[0]-u1[0]*u0[2], u1[0]*u0[1]-u1[1]*u0[0] };
      float l21 = sqrtf(c21[0]*c21[0]+c21[1]*c21[1]+c21[2]*c21[2]) + 1e-8f;
      float l10 = sqrtf(c10[0]*c10[0]+c10[1]*c10[1]+c10[2]*c10[2]) + 1e-8f;
      #pragma unroll
      for (int c = 0; c < 3; c++){ c21[c]/=l21; c10[c]/=l10; }
      float cosD = c21[0]*c10[0]+c21[1]*c10[1]+c21[2]*c10[2];
      cosD = fminf(fmaxf(cosD, -1.f + 1e-7f), 1.f - 1e-7f);
      float sdot = u2[0]*c10[0]+u2[1]*c10[1]+u2[2]*c10[2];
      float sgn = (sdot > 0.f) ? 1.f : ((sdot < 0.f) ? -1.f : 0.f);
      D = sgn * acosf(cosD);
    }
    Dv[t3] = D;
  }
  float x0[7] = { cosf(Dv[0]), cosf(Dv[1]), cosf(Dv[2]),
                  sinf(Dv[0]), sinf(Dv[1]), sinf(Dv[2]), 1.f };

  float v[7][3];
  #pragma unroll
  for (int a = 0; a < 4; a++){
    v[a][0] = bb[i*12 + a*3 + 0] - ca0;
    v[a][1] = bb[i*12 + a*3 + 1] - ca1;
    v[a][2] = bb[i*12 + a*3 + 2] - ca2;
  }
  if (i < NRES-1){
    float dx = bb[(i+1)*12+3] - ca0, dy = bb[(i+1)*12+4] - ca1, dz = bb[(i+1)*12+5] - ca2;
    float n = sqrtf(dx*dx+dy*dy+dz*dz) + 1e-8f;
    v[4][0]=dx/n; v[4][1]=dy/n; v[4][2]=dz/n;
  } else { v[4][0]=v[4][1]=v[4][2]=0.f; }
  if (i > 0){
    float dx = ca0 - bb[(i-1)*12+3], dy = ca1 - bb[(i-1)*12+4], dz = ca2 - bb[(i-1)*12+5];
    float n = sqrtf(dx*dx+dy*dy+dz*dz) + 1e-8f;
    v[5][0]=-dx/n; v[5][1]=-dy/n; v[5][2]=-dz/n;
  } else { v[5][0]=v[5][1]=v[5][2]=0.f; }
  {
    float b0 = ca0 - bb[i*12+0], b1 = ca1 - bb[i*12+1], b2 = ca2 - bb[i*12+2];
    float cc0 = bb[i*12+6] - ca0, cc1 = bb[i*12+7] - ca1, cc2 = bb[i*12+8] - ca2;
    float a0 = b1*cc2 - b2*cc1, a1 = b2*cc0 - b0*cc2, a2 = b0*cc1 - b1*cc0;
    v[6][0] = -0.58273431f*a0 + 0.56802827f*b0 - 0.54067466f*cc0;
    v[6][1] = -0.58273431f*a1 + 0.56802827f*b1 - 0.54067466f*cc1;
    v[6][2] = -0.58273431f*a2 + 0.56802827f*b2 - 0.54067466f*cc2;
  }
  #pragma unroll
  for (int q = 0; q < 7; q++){
    v[q][0]=fin0(v[q][0]); v[q][1]=fin0(v[q][1]); v[q][2]=fin0(v[q][2]);
  }

  float acc = 0.f;
  #pragma unroll
  for (int d = 0; d < 7; d++) acc = fmaf(x0[d], Wemb0[d*32 + lane], acc);
  for (int d = 0; d < 32; d++) acc = fmaf(lat[(i*4+0)*32 + d], Wemb0[(7+d)*32 + lane], acc);
  float h0r = fmaxf(acc, 0.f);
  g_h0[0][i*32 + lane] = h0r;

  float h1r[3];
  #pragma unroll
  for (int j = 0; j < 3; j++){
    float a2 = 0.f;
    #pragma unroll
    for (int d = 0; d < 7; d++) a2 = fmaf(v[d][j], Wemb1[d*32 + lane], a2);
    for (int d = 0; d < 32; d++) a2 = fmaf(lat[(i*4+1+j)*32 + d], Wemb1[(7+d)*32 + lane], a2);
    h1r[j] = a2;
    g_h1[0][(i*3+j)*32 + lane] = a2;
  }

  float hs = 0.f, hdv = 0.f;
  #pragma unroll
  for (int d = 0; d < 32; d++){
    float a = __shfl_sync(0xffffffffu, h0r, d);
    hs  = fmaf(a, __ldg(&Wss0[d*32+lane]), hs);
    hdv = fmaf(a, __ldg(&Wds0[d*32+lane]), hdv);
  }
  g_hsS[0][i*32+lane] = hs;
  g_hdS[0][i*32+lane] = hdv;
  #pragma unroll
  for (int c = 0; c < 3; c++){
    float hv = 0.f;
    #pragma unroll
    for (int d = 0; d < 32; d++)
      hv = fmaf(__shfl_sync(0xffffffffu, h1r[c], d), __ldg(&Wvs0[d*32+lane]), hv);
    g_hvS[0][c*NRES*32 + i*32 + lane] = hv;
  }
}

// ---------------- kNN: hybrid bitonic / serial-insertion top-32 ----------------
__device__ __forceinline__ unsigned long long shfx64(unsigned long long v, int m){
  return __shfl_xor_sync(0xffffffffu, v, m);
}

__global__ __launch_bounds__(256) void knn_kernel(const int* __restrict__ bid){
  int lane = threadIdx.x & 31;
  int i = blockIdx.x*8 + (threadIdx.x >> 5);
  if (i >= NRES) return;
  float4 qi = g_xca4[i];
  int b = bid[i];
  int lo = g_bstart[b], hi = g_bend[b];

  const unsigned long long INF = 0xFFFFFFFFFFFFFFFFull;
  unsigned long long state = INF;
  unsigned long long worst = INF;

  for (int j0 = lo; j0 < hi; j0 += 32){
    int j = j0 + lane;
    unsigned long long key = INF;
    if (j < hi && j != i){
      float4 qj = g_xca4[j];
      float d2 = fmaf(-2.f, qi.x*qj.x + qi.y*qj.y + qi.z*qj.z, qi.w + qj.w);
      unsigned int fb = __float_as_uint(d2);
      fb = (fb & 0x80000000u) ? ~fb : (fb | 0x80000000u);
      key = ((unsigned long long)fb << 32) | (unsigned int)j;
    }
    unsigned int qual = __ballot_sync(0xffffffffu, key < worst);
    if (!qual) continue;

    if (__popc(qual) >= 12){
      #pragma unroll
      for (int k = 2; k <= 32; k <<= 1){
        #pragma unroll
        for (int jj = k >> 1; jj > 0; jj >>= 1){
          unsigned long long o = shfx64(key, jj);
          bool up = ((lane & k) == 0);
          bool lower = ((lane & jj) == 0);
          bool keepmin = (up == lower);
          key = ((o < key) == keepmin) ? o : key;
        }
      }
      unsigned long long rev = shfx64(key, 31);
      unsigned long long m = (rev < state) ? rev : state;
      #pragma unroll
      for (int jj = 16; jj > 0; jj >>= 1){
        unsigned long long o = shfx64(m, jj);
        bool lower = ((lane & jj) == 0);
        m = ((o < m) == lower) ? o : m;
      }
      state = m;
      worst = __shfl_sync(0xffffffffu, state, 31);
    } else {
      while (qual){
        int src = __ffs(qual) - 1;
        qual &= qual - 1;
        unsigned long long x = __shfl_sync(0xffffffffu, key, src);
        unsigned int gmask = __ballot_sync(0xffffffffu, state > x);
        if (!gmask) continue;
        int pos = __ffs(gmask) - 1;
        unsigned long long up = __shfl_up_sync(0xffffffffu, state, 1);
        state = (lane < pos) ? state : ((lane == pos) ? x : up);
      }
      worst = __shfl_sync(0xffffffffu, state, 31);
    }
  }

  if (lane < KNN){
    g_src[i*KNN + lane] = (state == INF) ? i : (int)(unsigned int)(state & 0xFFFFFFFFull);
  }
}

// ---------------- phase 1 (layers 0..2): register weights, batched gathers ----------------
// Reads slot slotIn; epilogue writes ps/pd planes + hs/hd (+hv if DOHVN) to slot slotIn^1.
#define CHK 6
#define P1W 4
template<bool FIRST, bool DOHVN>
__global__ __launch_bounds__(128) void mp_phase1(int bufIn, int slotIn,
    const float* __restrict__ We1, const float* __restrict__ We2,
    const float* __restrict__ W0,  const float* __restrict__ W1,
    const float* __restrict__ Wu1,
    const float* __restrict__ Wssn, const float* __restrict__ Wdsn,
    const float* __restrict__ Wvsn)
{
  __shared__ __align__(16) float sE[P1W][CHK][32];
  __shared__ __align__(16) float sT[P1W][CHK][32];
  __shared__ int sSrc[P1W][32];

  int lane = threadIdx.x & 31;
  int w = threadIdx.x >> 5;
  int i = blockIdx.x*P1W + w;
  if (i >= NRES) return;
  int slotN = slotIn ^ 1;

  float w1r[32], w2r[32];
  #pragma unroll
  for (int d = 0; d < 32; d++){
    w1r[d] = __ldg(&We1[d*32 + lane]);
    w2r[d] = __ldg(&We2[d*32 + lane]);
  }

  if (lane < KNN) sSrc[w][lane] = g_src[i*KNN + lane];
  __syncwarp();

  float4 qi = make_float4(0.f,0.f,0.f,0.f);
  float mu = 0.f, fr = 0.f;
  if (FIRST){
    qi = g_xca4[i];
    if (lane < 16) mu = (float)lane * (20.f/15.f);
    else fr = expf(-((float)(2*((lane-16)&7))/16.f) * 9.210340371976184f);
  }

  const float* h0in = g_h0[bufIn];  float* h0out = g_h0[bufIn^1];
  const float* h1in = g_h1[bufIn];  float* h1out = g_h1[bufIn^1];
  const float* hsIn = g_hsS[slotIn];
  const float* hvIn = g_hvS[slotIn];

  float h0d = h0in[i*HDIM + lane];
  float hd  = g_hdS[slotIn][i*HDIM + lane];
  float acc0 = 0.f, av0 = 0.f, av1 = 0.f, av2 = 0.f;

  for (int c0 = 0; c0 < KNN; c0 += CHK){
    float efv[CHK], hsv[CHK], h0v[CHK];
    #pragma unroll
    for (int k = 0; k < CHK; k++){
      int s = sSrc[w][c0 + k];
      hsv[k] = hsIn[s*HDIM + lane];
      h0v[k] = h0in[s*HDIM + lane];
      if (FIRST){
        float4 qs = g_xca4[s];
        float dx = qi.x-qs.x, dy = qi.y-qs.y, dz = qi.z-qs.z;
        float dist = sqrtf(dx*dx + dy*dy + dz*dz);
        float val;
        if (lane < 16){ float t = (dist - mu) / 1.25f; val = expf(-t*t); }
        else { float a = (float)(s - i) * fr; val = (lane < 24) ? cosf(a) : sinf(a); }
        efv[k] = val;
        g_ef[((size_t)(i*KNN + c0 + k))*EFD + lane] = val;
      } else {
        efv[k] = g_ef[((size_t)(i*KNN + c0 + k))*EFD + lane];
      }
    }
    #pragma unroll
    for (int k = 0; k < CHK; k++) sE[w][k][lane] = efv[k];
    __syncwarp();
    #pragma unroll
    for (int k = 0; k < CHK; k++){
      float t0 = hd + hsv[k];
      float t1 = 0.f;
      #pragma unroll
      for (int d4 = 0; d4 < 8; d4++){
        float4 a = *(const float4*)&sE[w][k][d4*4];
        t0 = fmaf(a.x, w1r[d4*4+0], t0); t1 = fmaf(a.y, w1r[d4*4+1], t1);
        t0 = fmaf(a.z, w1r[d4*4+2], t0); t1 = fmaf(a.w, w1r[d4*4+3], t1);
      }
      sT[w][k][lane] = fmaxf(t0 + t1, 0.f);
    }
    __syncwarp();
    float gk[CHK];
    #pragma unroll
    for (int k = 0; k < CHK; k++){
      float g0 = 0.f, g1 = 0.f;
      #pragma unroll
      for (int d4 = 0; d4 < 8; d4++){
        float4 a = *(const float4*)&sT[w][k][d4*4];
        g0 = fmaf(a.x, w2r[d4*4+0], g0); g1 = fmaf(a.y, w2r[d4*4+1], g1);
        g0 = fmaf(a.z, w2r[d4*4+2], g0); g1 = fmaf(a.w, w2r[d4*4+3], g1);
      }
      gk[k] = g0 + g1;
    }
    #pragma unroll
    for (int k = 0; k < CHK; k++) acc0 = fmaf(gk[k], h0v[k], acc0);
    {
      float hvv[CHK];
      #pragma unroll
      for (int k = 0; k < CHK; k++) hvv[k] = hvIn[0*NRES*32 + sSrc[w][c0+k]*32 + lane];
      #pragma unroll
      for (int k = 0; k < CHK; k++) av0 = fmaf(gk[k], hvv[k], av0);
      #pragma unroll
      for (int k = 0; k < CHK; k++) hvv[k] = hvIn[1*NRES*32 + sSrc[w][c0+k]*32 + lane];
      #pragma unroll
      for (int k = 0; k < CHK; k++) av1 = fmaf(gk[k], hvv[k], av1);
      #pragma unroll
      for (int k = 0; k < CHK; k++) hvv[k] = hvIn[2*NRES*32 + sSrc[w][c0+k]*32 + lane];
      #pragma unroll
      for (int k = 0; k < CHK; k++) av2 = fmaf(gk[k], hvv[k], av2);
    }
    __syncwarp();
  }

  const float inv = 1.f/(float)KNN;
  acc0 *= inv;

  float u0 = 0.f, u1 = 0.f;
  #pragma unroll
  for (int d = 0; d < 32; d += 2){
    u0 = fmaf(__shfl_sync(0xffffffffu, acc0, d),   __ldg(&W0[d*32+lane]),     u0);
    u1 = fmaf(__shfl_sync(0xffffffffu, acc0, d+1), __ldg(&W0[(d+1)*32+lane]), u1);
  }
  float h0new = h0d + fmaxf(u0 + u1, 0.f);
  h0out[i*HDIM + lane] = h0new;

  av0 *= inv; av1 *= inv; av2 *= inv;
  float o0 = 0.f, o1 = 0.f, o2 = 0.f;
  #pragma unroll
  for (int d = 0; d < 32; d++){
    float wv = __ldg(&W1[d*32+lane]);
    o0 = fmaf(__shfl_sync(0xffffffffu, av0, d), wv, o0);
    o1 = fmaf(__shfl_sync(0xffffffffu, av1, d), wv, o1);
    o2 = fmaf(__shfl_sync(0xffffffffu, av2, d), wv, o2);
  }
  float h1n0 = h1in[(i*3+0)*HDIM + lane] + o0;
  float h1n1 = h1in[(i*3+1)*HDIM + lane] + o1;
  float h1n2 = h1in[(i*3+2)*HDIM + lane] + o2;
  h1out[(i*3+0)*HDIM + lane] = h1n0;
  h1out[(i*3+1)*HDIM + lane] = h1n1;
  h1out[(i*3+2)*HDIM + lane] = h1n2;

  // ps/pd planes for phase2(l)
  const float* U1b = Wu1 + 2048;
  const float* U1c = Wu1 + 4096;
  float psa = 0.f, psb = 0.f, pda = 0.f, pdb = 0.f;
  #pragma unroll
  for (int d = 0; d < 32; d++){
    float h = __shfl_sync(0xffffffffu, h0new, d);
    psa = fmaf(h, __ldg(&U1b[d*64 + lane]),      psa);
    psb = fmaf(h, __ldg(&U1b[d*64 + 32 + lane]), psb);
    pda = fmaf(h, __ldg(&U1c[d*64 + lane]),      pda);
    pdb = fmaf(h, __ldg(&U1c[d*64 + 32 + lane]), pdb);
  }
  g_ps2[0][i*32 + lane] = psa;
  g_ps2[1][i*32 + lane] = psb;
  g_pd2[0][i*32 + lane] = pda;
  g_pd2[1][i*32 + lane] = pdb;

  // next-layer hs/hd (+hv) -> slot slotN (activations hot in registers)
  float hsn = 0.f, hdn = 0.f;
  #pragma unroll
  for (int d = 0; d < 32; d++){
    float a = __shfl_sync(0xffffffffu, h0new, d);
    hsn = fmaf(a, __ldg(&Wssn[d*32+lane]), hsn);
    hdn = fmaf(a, __ldg(&Wdsn[d*32+lane]), hdn);
  }
  g_hsS[slotN][i*32+lane] = hsn;
  g_hdS[slotN][i*32+lane] = hdn;
  if (DOHVN){
    float hv0 = 0.f, hv1 = 0.f, hv2 = 0.f;
    #pragma unroll
    for (int d = 0; d < 32; d++){
      float wv = __ldg(&Wvsn[d*32+lane]);
      hv0 = fmaf(__shfl_sync(0xffffffffu, h1n0, d), wv, hv0);
      hv1 = fmaf(__shfl_sync(0xffffffffu, h1n1, d), wv, hv1);
      hv2 = fmaf(__shfl_sync(0xffffffffu, h1n2, d), wv, hv2);
    }
    g_hvS[slotN][0*NRES*32 + i*32 + lane] = hv0;
    g_hvS[slotN][1*NRES*32 + i*32 + lane] = hv1;
    g_hvS[slotN][2*NRES*32 + i*32 + lane] = hv2;
  }
}

// ---------------- phase 2: 2 warps per node, hidden-half split, no epilogue ----------------
// grid = NRES/2 blocks x 128 threads (exact; all threads reach __syncthreads)
__global__ __launch_bounds__(128) void mp_phase2(
    const float* __restrict__ Wu1, const float* __restrict__ Wu2)
{
  __shared__ __align__(16) float sE[2][CHK][32];
  __shared__ __align__(16) float sY[4][CHK][32];
  __shared__ __align__(16) float sO[2][CHK][32];
  __shared__ int sSrc[2][32];

  int lane = threadIdx.x & 31;
  int w = threadIdx.x >> 5;
  int nl = w >> 1;       // node within block
  int half = w & 1;      // hidden half
  int i = blockIdx.x*2 + nl;

  // own half's weight columns
  float u1r[32], w2r[32];
  #pragma unroll
  for (int d = 0; d < 32; d++){
    u1r[d] = __ldg(&Wu1[d*64 + half*32 + lane]);
    w2r[d] = __ldg(&Wu2[(half*32 + d)*32 + lane]);
  }

  if (half == 0 && lane < KNN) sSrc[nl][lane] = g_src[i*KNN + lane];
  __syncthreads();

  float pdh = g_pd2[half][i*32 + lane];

  for (int c0 = 0; c0 < KNN; c0 += CHK){
    float efv[CHK], psv[CHK];
    #pragma unroll
    for (int k = 0; k < CHK; k++){
      psv[k] = g_ps2[half][sSrc[nl][c0+k]*32 + lane];
      if (half == 0) efv[k] = g_ef[((size_t)(i*KNN + c0 + k))*EFD + lane];
    }
    if (half == 0){
      #pragma unroll
      for (int k = 0; k < CHK; k++) sE[nl][k][lane] = efv[k];
    }
    __syncthreads();
    // phase A: own y-half = relu(pd_h + ps_h + ef @ U1a[:,half])
    float yk[CHK];
    #pragma unroll
    for (int k = 0; k < CHK; k++){
      float y = pdh + psv[k];
      #pragma unroll
      for (int d4 = 0; d4 < 8; d4++){
        float4 a = *(const float4*)&sE[nl][k][d4*4];
        y = fmaf(a.x, u1r[d4*4+0], y); y = fmaf(a.y, u1r[d4*4+1], y);
        y = fmaf(a.z, u1r[d4*4+2], y); y = fmaf(a.w, u1r[d4*4+3], y);
      }
      yk[k] = fmaxf(y, 0.f);
    }
    #pragma unroll
    for (int k = 0; k < CHK; k++) sY[w][k][lane] = yk[k];
    __syncwarp();
    // phase B: partial output GEMV over own half
    float ok[CHK];
    #pragma unroll
    for (int k = 0; k < CHK; k++){
      float o = 0.f;
      #pragma unroll
      for (int j4 = 0; j4 < 8; j4++){
        float4 a = *(const float4*)&sY[w][k][j4*4];
        o = fmaf(a.x, w2r[j4*4+0], o); o = fmaf(a.y, w2r[j4*4+1], o);
        o = fmaf(a.z, w2r[j4*4+2], o); o = fmaf(a.w, w2r[j4*4+3], o);
      }
      ok[k] = o;
    }
    if (half == 1){
      #pragma unroll
      for (int k = 0; k < CHK; k++) sO[nl][k][lane] = ok[k];
    }
    __syncthreads();
    if (half == 0){
      #pragma unroll
      for (int k = 0; k < CHK; k++)
        g_ef[((size_t)(i*KNN + c0 + k))*EFD + lane] = efv[k] + ok[k] + sO[nl][k][lane];
    }
  }
}

// ---------------- LAST phase1 + decode fused (reads slot 1) ----------------
__global__ __launch_bounds__(128) void mp_last_decode(int bufIn,
    const float* __restrict__ We1, const float* __restrict__ We2,
    const float* __restrict__ W0,
    const float* __restrict__ rot,
    const float* __restrict__ Wp0, const float* __restrict__ Wt, const float* __restrict__ bt,
    const float* __restrict__ Wseq1, const float* __restrict__ bseq1,
    const float* __restrict__ Wseq2, const float* __restrict__ bseq2,
    const float* __restrict__ Wseq3, const float* __restrict__ bseq3,
    const float* __restrict__ lit_pos, const float* __restrict__ Wchi, const float* __restrict__ Wpsi,
    float* __restrict__ out)
{
  __shared__ __align__(16) float sE[P1W][CHK][32];
  __shared__ __align__(16) float sT[P1W][CHK][32];
  __shared__ float su[P1W][162];
  __shared__ int sSrc[P1W][32];

  int lane = threadIdx.x & 31;
  int w = threadIdx.x >> 5;
  int i = blockIdx.x*P1W + w;
  if (i >= NRES) return;

  float w1r[32], w2r[32];
  #pragma unroll
  for (int d = 0; d < 32; d++){
    w1r[d] = __ldg(&We1[d*32 + lane]);
    w2r[d] = __ldg(&We2[d*32 + lane]);
  }

  if (lane < KNN) sSrc[w][lane] = g_src[i*KNN + lane];
  __syncwarp();

  const float* h0in = g_h0[bufIn];
  const float* hsIn = g_hsS[1];

  float h0d = h0in[i*HDIM + lane];
  float hd  = g_hdS[1][i*HDIM + lane];
  float acc0 = 0.f;

  for (int c0 = 0; c0 < KNN; c0 += CHK){
    float efv[CHK], hsv[CHK], h0v[CHK];
    #pragma unroll
    for (int k = 0; k < CHK; k++){
      int s = sSrc[w][c0 + k];
      hsv[k] = hsIn[s*HDIM + lane];
      h0v[k] = h0in[s*HDIM + lane];
      efv[k] = g_ef[((size_t)(i*KNN + c0 + k))*EFD + lane];
    }
    #pragma unroll
    for (int k = 0; k < CHK; k++) sE[w][k][lane] = efv[k];
    __syncwarp();
    #pragma unroll
    for (int k = 0; k < CHK; k++){
      float t0 = hd + hsv[k];
      float t1 = 0.f;
      #pragma unroll
      for (int d4 = 0; d4 < 8; d4++){
        float4 a = *(const float4*)&sE[w][k][d4*4];
        t0 = fmaf(a.x, w1r[d4*4+0], t0); t1 = fmaf(a.y, w1r[d4*4+1], t1);
        t0 = fmaf(a.z, w1r[d4*4+2], t0); t1 = fmaf(a.w, w1r[d4*4+3], t1);
      }
      sT[w][k][lane] = fmaxf(t0 + t1, 0.f);
    }
    __syncwarp();
    #pragma unroll
    for (int k = 0; k < CHK; k++){
      float g0 = 0.f, g1 = 0.f;
      #pragma unroll
      for (int d4 = 0; d4 < 8; d4++){
        float4 a = *(const float4*)&sT[w][k][d4*4];
        g0 = fmaf(a.x, w2r[d4*4+0], g0); g1 = fmaf(a.y, w2r[d4*4+1], g1);
        g0 = fmaf(a.z, w2r[d4*4+2], g0); g1 = fmaf(a.w, w2r[d4*4+3], g1);
      }
      acc0 = fmaf(g0 + g1, h0v[k], acc0);
    }
    __syncwarp();
  }

  acc0 *= 1.f/(float)KNN;
  float u0 = 0.f, u1 = 0.f;
  #pragma unroll
  for (int d = 0; d < 32; d += 2){
    u0 = fmaf(__shfl_sync(0xffffffffu, acc0, d),   __ldg(&W0[d*32+lane]),     u0);
    u1 = fmaf(__shfl_sync(0xffffffffu, acc0, d+1), __ldg(&W0[(d+1)*32+lane]), u1);
  }
  float h0c = h0d + fmaxf(u0 + u1, 0.f);

  // ---- decode (identical numerics) ----
  float t0 = 0.f;
  #pragma unroll
  for (int d = 0; d < 32; d++) t0 = fmaf(__shfl_sync(0xffffffffu, h0c, d), Wp0[d*32 + lane], t0);
  t0 = fmaxf(t0, 0.f);
  #pragma unroll
  for (int r = 0; r < 6; r++){
    int idx = r*32 + lane;
    int widx = idx < 162 ? idx : 161;
    float u = bt[widx];
    #pragma unroll
    for (int c = 0; c < 32; c++) u = fmaf(__shfl_sync(0xffffffffu, t0, c), Wt[c*162 + widx], u);
    if (idx < 162) su[w][idx] = u;
  }
  __syncwarp();
  for (int j = lane; j < 81; j += 32){
    float a = su[w][2*j], b = su[w][2*j+1];
    float ea = a + 1e-8f, eb = b + 1e-8f;
    float den = sqrtf(ea*ea + eb*eb);
    su[w][2*j]   = a / den;
    su[w][2*j+1] = b / den;
  }
  __syncwarp();
  float p0 = su[w][0], p1 = su[w][1];
  float r00=rot[i*9+0], r01=rot[i*9+1], r02=rot[i*9+2];
  float r10=rot[i*9+3], r11=rot[i*9+4], r12=rot[i*9+5];
  float r20=rot[i*9+6], r21=rot[i*9+7], r22=rot[i*9+8];

  for (int m = lane; m < 91; m += 32){
    int k, a;
    if (m < 4){ k = 0; a = m; }
    else { k = c_aa[m-4]; a = 4 + c_off[m-4]; }
    float chi[8];
    #pragma unroll
    for (int t = 0; t < 4; t++){
      chi[2*t]   = su[w][2*(1 + k*4 + t)];
      chi[2*t+1] = su[w][2*(1 + k*4 + t) + 1];
    }
    float l[3];
    #pragma unroll
    for (int j = 0; j < 3; j++){
      float acc = lit_pos[(k*14 + a)*3 + j];
      #pragma unroll
      for (int c = 0; c < 8; c++) acc = fmaf(chi[c], Wchi[(c*14 + a)*3 + j], acc);
      acc = fmaf(p0, Wpsi[(0*14 + a)*3 + j], acc);
      acc = fmaf(p1, Wpsi[(1*14 + a)*3 + j], acc);
      l[j] = acc;
    }
    out[((size_t)i*91 + m)*3 + 0] = r00*l[0] + r01*l[1] + r02*l[2];
    out[((size_t)i*91 + m)*3 + 1] = r10*l[0] + r11*l[1] + r12*l[2];
    out[((size_t)i*91 + m)*3 + 2] = r20*l[0] + r21*l[1] + r22*l[2];
  }

  float s1a = bseq1[lane], s1b = bseq1[32 + lane];
  #pragma unroll
  for (int d = 0; d < 32; d++){
    float h = __shfl_sync(0xffffffffu, h0c, d);
    s1a = fmaf(h, Wseq1[d*64 + lane],      s1a);
    s1b = fmaf(h, Wseq1[d*64 + 32 + lane], s1b);
  }
  s1a = fmaxf(s1a, 0.f); s1b = fmaxf(s1b, 0.f);
  float s2 = bseq2[lane];
  #pragma unroll
  for (int h = 0; h < 32; h++) s2 = fmaf(__shfl_sync(0xffffffffu, s1a, h), Wseq2[h*32 + lane], s2);
  #pragma unroll
  for (int h = 0; h < 32; h++) s2 = fmaf(__shfl_sync(0xffffffffu, s1b, h), Wseq2[(32+h)*32 + lane], s2);
  s2 = fmaxf(s2, 0.f);
  int ll = lane < 20 ? lane : 19;
  float lg = bseq3[ll];
  #pragma unroll
  for (int c = 0; c < 32; c++) lg = fmaf(__shfl_sync(0xffffffffu, s2, c), Wseq3[c*20 + ll], lg);
  float mv = (lane < 20) ? lg : -3.0e38f;
  #pragma unroll
  for (int o = 16; o > 0; o >>= 1) mv = fmaxf(mv, __shfl_xor_sync(0xffffffffu, mv, o));
  float ex = (lane < 20) ? expf(lg - mv) : 0.f;
  #pragma unroll
  for (int o = 16; o > 0; o >>= 1) ex += __shfl_xor_sync(0xffffffffu, ex, o);
  if (lane < 20) out[(size_t)NRES*273 + (size_t)i*20 + lane] = lg - mv - logf(ex);
}

// ---------------- launch ----------------
extern "C" void kernel_launch(void* const* d_in, const int* in_sizes, int n_in,
                              void* d_out, int out_size)
{
  const float* bb      = (const float*)d_in[0];
  const float* latent  = (const float*)d_in[1];
  const float* rrot    = (const float*)d_in[2];
  const float* rtrans  = (const float*)d_in[3];
  const float* Wemb0   = (const float*)d_in[4];
  const float* Wemb1   = (const float*)d_in[5];
  const float* We1s    = (const float*)d_in[6];
  const float* Wss     = (const float*)d_in[7];
  const float* Wds     = (const float*)d_in[8];
  const float* We2s    = (const float*)d_in[9];
  const float* Wvs     = (const float*)d_in[10];
  const float* W0s     = (const float*)d_in[11];
  const float* W1s     = (const float*)d_in[12];
  const float* Wu1s    = (const float*)d_in[13];
  const float* Wu2s    = (const float*)d_in[14];
  const float* Wp0     = (const float*)d_in[15];
  const float* Wt      = (const float*)d_in[16];
  const float* bt      = (const float*)d_in[17];
  const float* Wseq1   = (const float*)d_in[18];
  const float* bseq1   = (const float*)d_in[19];
  const float* Wseq2   = (const float*)d_in[20];
  const float* bseq2   = (const float*)d_in[21];
  const float* Wseq3   = (const float*)d_in[22];
  const float* bseq3   = (const float*)d_in[23];
  const float* lit_pos = (const float*)d_in[24];
  const float* Wchi    = (const float*)d_in[25];
  const float* Wpsi    = (const float*)d_in[26];
  const int*   bids    = (const int*)d_in[28];
  float* out = (float*)d_out;

  const int GP = (NRES + P1W - 1) / P1W;   // 2500
  const int GP2 = NRES / 2;                // 5000 (exact)

  init_ranges_kernel<<<1, 32>>>();
  batch_range_kernel<<<(NRES+255)/256, 256>>>(bids);
  node_embed_kernel<<<1250, 256>>>(bb, latent, Wemb0, Wemb1, Wss, Wds, Wvs);
  knn_kernel<<<1250, 256>>>(bids);

  // layer 0: buf0 -> buf1; reads slot0, writes slot1 precomputes
  mp_phase1<true,true><<<GP, 128>>>(0, 0, We1s, We2s, W0s, W1s, Wu1s,
      Wss + 1024, Wds + 1024, Wvs + 1024);
  mp_phase2<<<GP2, 128>>>(Wu1s, Wu2s);

  // layer 1: buf1 -> buf0; reads slot1, writes slot0
  mp_phase1<false,true><<<GP, 128>>>(1, 1,
      We1s + 1024, We2s + 1024, W0s + 1024, W1s + 1024, Wu1s + 6144,
      Wss + 2048, Wds + 2048, Wvs + 2048);
  mp_phase2<<<GP2, 128>>>(Wu1s + 6144, Wu2s + 2048);

  // layer 2: buf0 -> buf1; reads slot0, writes slot1 (no hv for last layer)
  mp_phase1<false,false><<<GP, 128>>>(0, 0,
      We1s + 2048, We2s + 2048, W0s + 2048, W1s + 2048, Wu1s + 2*6144,
      Wss + 3072, Wds + 3072, Wvs + 3072);
  mp_phase2<<<GP2, 128>>>(Wu1s + 2*6144, Wu2s + 2*2048);

  // layer 3 (LAST) fused with decode: reads buf1 + slot1
  mp_last_decode<<<GP, 128>>>(1,
      We1s + 3072, We2s + 3072, W0s + 3072,
      rrot, Wp0, Wt, bt,
      Wseq1, bseq1, Wseq2, bseq2, Wseq3, bseq3,
      lit_pos, Wchi, Wpsi, out);
}

// round 16
// speedup vs baseline: 1.0367x; 1.0367x over previous
#include <cuda_runtime.h>
#include <math.h>

#define NRES 10000
#define KNN 30
#define HDIM 32
#define EFD 32
#define NEDGE (NRES*KNN)

// ---------------- device scratch ----------------
__device__ float g_h0[2][NRES*HDIM];
__device__ float g_h1[2][NRES*3*HDIM];
__device__ float g_ef[NEDGE*EFD];
__device__ int   g_src[NEDGE];
__device__ float4 g_xca4[NRES];
__device__ int   g_bstart[8];
__device__ int   g_bend[8];
// parity-slotted (writer = phase1(l) epilogue -> slot (l+1)&1; reader = phase1(l+1))
__device__ float g_hsS[2][NRES*HDIM];
__device__ float g_hdS[2][NRES*HDIM];
__device__ float g_hvS[2][3*NRES*HDIM];   // plane-major within slot
// produced by phase1(l), consumed by phase2(l)
__device__ float2 g_psp[NRES*HDIM];       // (psa,psb) per (node,lane)
__device__ float  g_pd[NRES*64];

__constant__ int c_aa[87] = {
  0,
  1,1,1,1,1,1,1, 2,2,2,2, 3,3,3,3, 4,4, 5,5,5,5,5, 6,6,6,6,6,
  8,8,8,8,8,8, 9,9,9,9, 10,10,10,10, 11,11,11,11,11, 12,12,12,12,
  13,13,13,13,13,13,13, 14,14,14, 15,15, 16,16,16,
  17,17,17,17,17,17,17,17,17,17, 18,18,18,18,18,18,18,18, 19,19,19
};
__constant__ int c_off[87] = {
  0,
  0,1,2,3,4,5,6, 0,1,2,3, 0,1,2,3, 0,1, 0,1,2,3,4, 0,1,2,3,4,
  0,1,2,3,4,5, 0,1,2,3, 0,1,2,3, 0,1,2,3,4, 0,1,2,3,
  0,1,2,3,4,5,6, 0,1,2, 0,1, 0,1,2,
  0,1,2,3,4,5,6,7,8,9, 0,1,2,3,4,5,6,7, 0,1,2
};

__device__ __forceinline__ float fin0(float v){ return isfinite(v) ? v : 0.f; }

// ---------------- batch ranges ----------------
__global__ void init_ranges_kernel(){
  int t = threadIdx.x;
  if (t < 8){ g_bstart[t] = NRES; g_bend[t] = 0; }
}
__global__ void batch_range_kernel(const int* __restrict__ bid){
  int i = blockIdx.x*blockDim.x + threadIdx.x;
  if (i >= NRES) return;
  int b = bid[i];
  atomicMin(&g_bstart[b], i);
  atomicMax(&g_bend[b], i+1);
}

// ---------------- node features + embeddings + layer-0 precompute (slot 0) ----------------
__global__ __launch_bounds__(256) void node_embed_kernel(
    const float* __restrict__ bb, const float* __restrict__ lat,
    const float* __restrict__ Wemb0, const float* __restrict__ Wemb1,
    const float* __restrict__ Wss0, const float* __restrict__ Wds0,
    const float* __restrict__ Wvs0)
{
  int lane = threadIdx.x & 31;
  int i = blockIdx.x*8 + (threadIdx.x >> 5);
  if (i >= NRES) return;

  float ca0 = bb[i*12+3], ca1 = bb[i*12+4], ca2 = bb[i*12+5];
  if (lane == 0){
    g_xca4[i] = make_float4(ca0, ca1, ca2, ca0*ca0 + ca1*ca1 + ca2*ca2);
  }

  float Dv[3];
  #pragma unroll
  for (int t3 = 0; t3 < 3; t3++){
    int t = 3*i + t3;
    float D = 0.f;
    if (t >= 1 && t <= 3*NRES - 3){
      int d0 = t - 1;
      float x[4][3];
      #pragma unroll
      for (int q = 0; q < 4; q++){
        int m = d0 + q; int r = m/3; int am = m - r*3;
        x[q][0] = bb[r*12 + am*3 + 0];
        x[q][1] = bb[r*12 + am*3 + 1];
        x[q][2] = bb[r*12 + am*3 + 2];
      }
      float u2[3], u1[3], u0[3];
      #pragma unroll
      for (int c = 0; c < 3; c++){ u2[c]=x[1][c]-x[0][c]; u1[c]=x[2][c]-x[1][c]; u0[c]=x[3][c]-x[2][c]; }
      float n2n = sqrtf(u2[0]*u2[0]+u2[1]*u2[1]+u2[2]*u2[2]) + 1e-8f;
      float n1n = sqrtf(u1[0]*u1[0]+u1[1]*u1[1]+u1[2]*u1[2]) + 1e-8f;
      float n0n = sqrtf(u0[0]*u0[0]+u0[1]*u0[1]+u0[2]*u0[2]) + 1e-8f;
      #pragma unroll
      for (int c = 0; c < 3; c++){ u2[c]/=n2n; u1[c]/=n1n; u0[c]/=n0n; }
      float c21[3] = { u2[1]*u1[2]-u2[2]*u1[1], u2[2]*u1[0]-u2[0]*u1[2], u2[0]*u1[1]-u2[1]*u1[0] };
      float c10[3] = { u1[1]*u0[2]-u1[2]*u0[1], u1[2]*u0[0]-u1[0]*u0[2], u1[0]*u0[1]-u1[1]*u0[0] };
      float l21 = sqrtf(c21[0]*c21[0]+c21[1]*c21[1]+c21[2]*c21[2]) + 1e-8f;
      float l10 = sqrtf(c10[0]*c10[0]+c10[1]*c10[1]+c10[2]*c10[2]) + 1e-8f;
      #pragma unroll
      for (int c = 0; c < 3; c++){ c21[c]/=l21; c10[c]/=l10; }
      float cosD = c21[0]*c10[0]+c21[1]*c10[1]+c21[2]*c10[2];
      cosD = fminf(fmaxf(cosD, -1.f + 1e-7f), 1.f - 1e-7f);
      float sdot = u2[0]*c10[0]+u2[1]*c10[1]+u2[2]*c10[2];
      float sgn = (sdot > 0.f) ? 1.f : ((sdot < 0.f) ? -1.f : 0.f);
      D = sgn * acosf(cosD);
    }
    Dv[t3] = D;
  }
  float x0[7] = { cosf(Dv[0]), cosf(Dv[1]), cosf(Dv[2]),
                  sinf(Dv[0]), sinf(Dv[1]), sinf(Dv[2]), 1.f };

  float v[7][3];
  #pragma unroll
  for (int a = 0; a < 4; a++){
    v[a][0] = bb[i*12 + a*3 + 0] - ca0;
    v[a][1] = bb[i*12 + a*3 + 1] - ca1;
    v[a][2] = bb[i*12 + a*3 + 2] - ca2;
  }
  if (i < NRES-1){
    float dx = bb[(i+1)*12+3] - ca0, dy = bb[(i+1)*12+4] - ca1, dz = bb[(i+1)*12+5] - ca2;
    float n = sqrtf(dx*dx+dy*dy+dz*dz) + 1e-8f;
    v[4][0]=dx/n; v[4][1]=dy/n; v[4][2]=dz/n;
  } else { v[4][0]=v[4][1]=v[4][2]=0.f; }
  if (i > 0){
    float dx = ca0 - bb[(i-1)*12+3], dy = ca1 - bb[(i-1)*12+4], dz = ca2 - bb[(i-1)*12+5];
    float n = sqrtf(dx*dx+dy*dy+dz*dz) + 1e-8f;
    v[5][0]=-dx/n; v[5][1]=-dy/n; v[5][2]=-dz/n;
  } else { v[5][0]=v[5][1]=v[5][2]=0.f; }
  {
    float b0 = ca0 - bb[i*12+0], b1 = ca1 - bb[i*12+1], b2 = ca2 - bb[i*12+2];
    float cc0 = bb[i*12+6] - ca0, cc1 = bb[i*12+7] - ca1, cc2 = bb[i*12+8] - ca2;
    float a0 = b1*cc2 - b2*cc1, a1 = b2*cc0 - b0*cc2, a2 = b0*cc1 - b1*cc0;
    v[6][0] = -0.58273431f*a0 + 0.56802827f*b0 - 0.54067466f*cc0;
    v[6][1] = -0.58273431f*a1 + 0.56802827f*b1 - 0.54067466f*cc1;
    v[6][2] = -0.58273431f*a2 + 0.56802827f*b2 - 0.54067466f*cc2;
  }
  #pragma unroll
  for (int q = 0; q < 7; q++){
    v[q][0]=fin0(v[q][0]); v[q][1]=fin0(v[q][1]); v[q][2]=fin0(v[q][2]);
  }

  float acc = 0.f;
  #pragma unroll
  for (int d = 0; d < 7; d++) acc = fmaf(x0[d], Wemb0[d*32 + lane], acc);
  for (int d = 0; d < 32; d++) acc = fmaf(lat[(i*4+0)*32 + d], Wemb0[(7+d)*32 + lane], acc);
  float h0r = fmaxf(acc, 0.f);
  g_h0[0][i*32 + lane] = h0r;

  float h1r[3];
  #pragma unroll
  for (int j = 0; j < 3; j++){
    float a2 = 0.f;
    #pragma unroll
    for (int d = 0; d < 7; d++) a2 = fmaf(v[d][j], Wemb1[d*32 + lane], a2);
    for (int d = 0; d < 32; d++) a2 = fmaf(lat[(i*4+1+j)*32 + d], Wemb1[(7+d)*32 + lane], a2);
    h1r[j] = a2;
    g_h1[0][(i*3+j)*32 + lane] = a2;
  }

  float hs = 0.f, hdv = 0.f;
  #pragma unroll
  for (int d = 0; d < 32; d++){
    float a = __shfl_sync(0xffffffffu, h0r, d);
    hs  = fmaf(a, __ldg(&Wss0[d*32+lane]), hs);
    hdv = fmaf(a, __ldg(&Wds0[d*32+lane]), hdv);
  }
  g_hsS[0][i*32+lane] = hs;
  g_hdS[0][i*32+lane] = hdv;
  #pragma unroll
  for (int c = 0; c < 3; c++){
    float hv = 0.f;
    #pragma unroll
    for (int d = 0; d < 32; d++)
      hv = fmaf(__shfl_sync(0xffffffffu, h1r[c], d), __ldg(&Wvs0[d*32+lane]), hv);
    g_hvS[0][c*NRES*32 + i*32 + lane] = hv;
  }
}

// ---------------- kNN: hybrid bitonic / serial-insertion top-32 ----------------
__device__ __forceinline__ unsigned long long shfx64(unsigned long long v, int m){
  return __shfl_xor_sync(0xffffffffu, v, m);
}

__global__ __launch_bounds__(256) void knn_kernel(const int* __restrict__ bid){
  int lane = threadIdx.x & 31;
  int i = blockIdx.x*8 + (threadIdx.x >> 5);
  if (i >= NRES) return;
  float4 qi = g_xca4[i];
  int b = bid[i];
  int lo = g_bstart[b], hi = g_bend[b];

  const unsigned long long INF = 0xFFFFFFFFFFFFFFFFull;
  unsigned long long state = INF;
  unsigned long long worst = INF;

  for (int j0 = lo; j0 < hi; j0 += 32){
    int j = j0 + lane;
    unsigned long long key = INF;
    if (j < hi && j != i){
      float4 qj = g_xca4[j];
      float d2 = fmaf(-2.f, qi.x*qj.x + qi.y*qj.y + qi.z*qj.z, qi.w + qj.w);
      unsigned int fb = __float_as_uint(d2);
      fb = (fb & 0x80000000u) ? ~fb : (fb | 0x80000000u);
      key = ((unsigned long long)fb << 32) | (unsigned int)j;
    }
    unsigned int qual = __ballot_sync(0xffffffffu, key < worst);
    if (!qual) continue;

    if (__popc(qual) >= 12){
      #pragma unroll
      for (int k = 2; k <= 32; k <<= 1){
        #pragma unroll
        for (int jj = k >> 1; jj > 0; jj >>= 1){
          unsigned long long o = shfx64(key, jj);
          bool up = ((lane & k) == 0);
          bool lower = ((lane & jj) == 0);
          bool keepmin = (up == lower);
          key = ((o < key) == keepmin) ? o : key;
        }
      }
      unsigned long long rev = shfx64(key, 31);
      unsigned long long m = (rev < state) ? rev : state;
      #pragma unroll
      for (int jj = 16; jj > 0; jj >>= 1){
        unsigned long long o = shfx64(m, jj);
        bool lower = ((lane & jj) == 0);
        m = ((o < m) == lower) ? o : m;
      }
      state = m;
      worst = __shfl_sync(0xffffffffu, state, 31);
    } else {
      while (qual){
        int src = __ffs(qual) - 1;
        qual &= qual - 1;
        unsigned long long x = __shfl_sync(0xffffffffu, key, src);
        unsigned int gmask = __ballot_sync(0xffffffffu, state > x);
        if (!gmask) continue;
        int pos = __ffs(gmask) - 1;
        unsigned long long up = __shfl_up_sync(0xffffffffu, state, 1);
        state = (lane < pos) ? state : ((lane == pos) ? x : up);
      }
      worst = __shfl_sync(0xffffffffu, state, 31);
    }
  }

  if (lane < KNN){
    g_src[i*KNN + lane] = (state == INF) ? i : (int)(unsigned int)(state & 0xFFFFFFFFull);
  }
}

// ---------------- phase 1 (layers 0..2): register weights, batched gathers ----------------
// Reads slot slotIn; epilogue writes ps/pd + hs/hd (+hv if DOHVN) to slot slotIn^1.
#define CHK 6
#define P1W 4
template<bool FIRST, bool DOHVN>
__global__ __launch_bounds__(128) void mp_phase1(int bufIn, int slotIn,
    const float* __restrict__ We1, const float* __restrict__ We2,
    const float* __restrict__ W0,  const float* __restrict__ W1,
    const float* __restrict__ Wu1,
    const float* __restrict__ Wssn, const float* __restrict__ Wdsn,
    const float* __restrict__ Wvsn)
{
  __shared__ __align__(16) float sE[P1W][CHK][32];
  __shared__ __align__(16) float sT[P1W][CHK][32];
  __shared__ int sSrc[P1W][32];

  int lane = threadIdx.x & 31;
  int w = threadIdx.x >> 5;
  int i = blockIdx.x*P1W + w;
  if (i >= NRES) return;
  int slotN = slotIn ^ 1;

  float w1r[32], w2r[32];
  #pragma unroll
  for (int d = 0; d < 32; d++){
    w1r[d] = __ldg(&We1[d*32 + lane]);
    w2r[d] = __ldg(&We2[d*32 + lane]);
  }

  if (lane < KNN) sSrc[w][lane] = g_src[i*KNN + lane];
  __syncwarp();

  float4 qi = make_float4(0.f,0.f,0.f,0.f);
  float mu = 0.f, fr = 0.f;
  if (FIRST){
    qi = g_xca4[i];
    if (lane < 16) mu = (float)lane * (20.f/15.f);
    else fr = expf(-((float)(2*((lane-16)&7))/16.f) * 9.210340371976184f);
  }

  const float* h0in = g_h0[bufIn];  float* h0out = g_h0[bufIn^1];
  const float* h1in = g_h1[bufIn];  float* h1out = g_h1[bufIn^1];
  const float* hsIn = g_hsS[slotIn];
  const float* hvIn = g_hvS[slotIn];

  float h0d = h0in[i*HDIM + lane];
  float hd  = g_hdS[slotIn][i*HDIM + lane];
  float acc0 = 0.f, av0 = 0.f, av1 = 0.f, av2 = 0.f;

  for (int c0 = 0; c0 < KNN; c0 += CHK){
    float efv[CHK], hsv[CHK], h0v[CHK];
    #pragma unroll
    for (int k = 0; k < CHK; k++){
      int s = sSrc[w][c0 + k];
      hsv[k] = hsIn[s*HDIM + lane];
      h0v[k] = h0in[s*HDIM + lane];
      if (FIRST){
        float4 qs = g_xca4[s];
        float dx = qi.x-qs.x, dy = qi.y-qs.y, dz = qi.z-qs.z;
        float dist = sqrtf(dx*dx + dy*dy + dz*dz);
        float val;
        if (lane < 16){ float t = (dist - mu) / 1.25f; val = expf(-t*t); }
        else { float a = (float)(s - i) * fr; val = (lane < 24) ? cosf(a) : sinf(a); }
        efv[k] = val;
        g_ef[((size_t)(i*KNN + c0 + k))*EFD + lane] = val;
      } else {
        efv[k] = g_ef[((size_t)(i*KNN + c0 + k))*EFD + lane];
      }
    }
    #pragma unroll
    for (int k = 0; k < CHK; k++) sE[w][k][lane] = efv[k];
    __syncwarp();
    #pragma unroll
    for (int k = 0; k < CHK; k++){
      float t0 = hd + hsv[k];
      float t1 = 0.f;
      #pragma unroll
      for (int d4 = 0; d4 < 8; d4++){
        float4 a = *(const float4*)&sE[w][k][d4*4];
        t0 = fmaf(a.x, w1r[d4*4+0], t0); t1 = fmaf(a.y, w1r[d4*4+1], t1);
        t0 = fmaf(a.z, w1r[d4*4+2], t0); t1 = fmaf(a.w, w1r[d4*4+3], t1);
      }
      sT[w][k][lane] = fmaxf(t0 + t1, 0.f);
    }
    __syncwarp();
    float gk[CHK];
    #pragma unroll
    for (int k = 0; k < CHK; k++){
      float g0 = 0.f, g1 = 0.f;
      #pragma unroll
      for (int d4 = 0; d4 < 8; d4++){
        float4 a = *(const float4*)&sT[w][k][d4*4];
        g0 = fmaf(a.x, w2r[d4*4+0], g0); g1 = fmaf(a.y, w2r[d4*4+1], g1);
        g0 = fmaf(a.z, w2r[d4*4+2], g0); g1 = fmaf(a.w, w2r[d4*4+3], g1);
      }
      gk[k] = g0 + g1;
    }
    #pragma unroll
    for (int k = 0; k < CHK; k++) acc0 = fmaf(gk[k], h0v[k], acc0);
    {
      float hvv[CHK];
      #pragma unroll
      for (int k = 0; k < CHK; k++) hvv[k] = hvIn[0*NRES*32 + sSrc[w][c0+k]*32 + lane];
      #pragma unroll
      for (int k = 0; k < CHK; k++) av0 = fmaf(gk[k], hvv[k], av0);
      #pragma unroll
      for (int k = 0; k < CHK; k++) hvv[k] = hvIn[1*NRES*32 + sSrc[w][c0+k]*32 + lane];
      #pragma unroll
      for (int k = 0; k < CHK; k++) av1 = fmaf(gk[k], hvv[k], av1);
      #pragma unroll
      for (int k = 0; k < CHK; k++) hvv[k] = hvIn[2*NRES*32 + sSrc[w][c0+k]*32 + lane];
      #pragma unroll
      for (int k = 0; k < CHK; k++) av2 = fmaf(gk[k], hvv[k], av2);
    }
    __syncwarp();
  }

  const float inv = 1.f/(float)KNN;
  acc0 *= inv;

  float u0 = 0.f, u1 = 0.f;
  #pragma unroll
  for (int d = 0; d < 32; d += 2){
    u0 = fmaf(__shfl_sync(0xffffffffu, acc0, d),   __ldg(&W0[d*32+lane]),     u0);
    u1 = fmaf(__shfl_sync(0xffffffffu, acc0, d+1), __ldg(&W0[(d+1)*32+lane]), u1);
  }
  float h0new = h0d + fmaxf(u0 + u1, 0.f);
  h0out[i*HDIM + lane] = h0new;

  av0 *= inv; av1 *= inv; av2 *= inv;
  float o0 = 0.f, o1 = 0.f, o2 = 0.f;
  #pragma unroll
  for (int d = 0; d < 32; d++){
    float wv = __ldg(&W1[d*32+lane]);
    o0 = fmaf(__shfl_sync(0xffffffffu, av0, d), wv, o0);
    o1 = fmaf(__shfl_sync(0xffffffffu, av1, d), wv, o1);
    o2 = fmaf(__shfl_sync(0xffffffffu, av2, d), wv, o2);
  }
  float h1n0 = h1in[(i*3+0)*HDIM + lane] + o0;
  float h1n1 = h1in[(i*3+1)*HDIM + lane] + o1;
  float h1n2 = h1in[(i*3+2)*HDIM + lane] + o2;
  h1out[(i*3+0)*HDIM + lane] = h1n0;
  h1out[(i*3+1)*HDIM + lane] = h1n1;
  h1out[(i*3+2)*HDIM + lane] = h1n2;

  // ps/pd for phase2(l)
  const float* U1b = Wu1 + 2048;
  const float* U1c = Wu1 + 4096;
  float psa = 0.f, psb = 0.f, pda = 0.f, pdb = 0.f;
  #pragma unroll
  for (int d = 0; d < 32; d++){
    float h = __shfl_sync(0xffffffffu, h0new, d);
    psa = fmaf(h, __ldg(&U1b[d*64 + lane]),      psa);
    psb = fmaf(h, __ldg(&U1b[d*64 + 32 + lane]), psb);
    pda = fmaf(h, __ldg(&U1c[d*64 + lane]),      pda);
    pdb = fmaf(h, __ldg(&U1c[d*64 + 32 + lane]), pdb);
  }
  g_psp[i*32 + lane] = make_float2(psa, psb);
  g_pd[i*64 + lane]      = pda;
  g_pd[i*64 + 32 + lane] = pdb;

  // next-layer hs/hd (+hv) -> slot slotN (activations hot in registers)
  float hsn = 0.f, hdn = 0.f;
  #pragma unroll
  for (int d = 0; d < 32; d++){
    float a = __shfl_sync(0xffffffffu, h0new, d);
    hsn = fmaf(a, __ldg(&Wssn[d*32+lane]), hsn);
    hdn = fmaf(a, __ldg(&Wdsn[d*32+lane]), hdn);
  }
  g_hsS[slotN][i*32+lane] = hsn;
  g_hdS[slotN][i*32+lane] = hdn;
  if (DOHVN){
    float hv0 = 0.f, hv1 = 0.f, hv2 = 0.f;
    #pragma unroll
    for (int d = 0; d < 32; d++){
      float wv = __ldg(&Wvsn[d*32+lane]);
      hv0 = fmaf(__shfl_sync(0xffffffffu, h1n0, d), wv, hv0);
      hv1 = fmaf(__shfl_sync(0xffffffffu, h1n1, d), wv, hv1);
      hv2 = fmaf(__shfl_sync(0xffffffffu, h1n2, d), wv, hv2);
    }
    g_hvS[slotN][0*NRES*32 + i*32 + lane] = hv0;
    g_hvS[slotN][1*NRES*32 + i*32 + lane] = hv1;
    g_hvS[slotN][2*NRES*32 + i*32 + lane] = hv2;
  }
}

// ---------------- phase 2 (round-14 form, epilogue-free) ----------------
__global__ __launch_bounds__(128) void mp_phase2(
    const float* __restrict__ Wu1, const float* __restrict__ Wu2)
{
  __shared__ __align__(16) float sE[P1W][CHK][32];
  __shared__ __align__(16) float sY[P1W][CHK][64];
  __shared__ int sSrc[P1W][32];

  int lane = threadIdx.x & 31;
  int w = threadIdx.x >> 5;
  int i = blockIdx.x*P1W + w;
  if (i >= NRES) return;

  float u1r0[32], u1r1[32], w2A[32], w2B[32];
  #pragma unroll
  for (int d = 0; d < 32; d++){
    u1r0[d] = __ldg(&Wu1[d*64 + lane]);
    u1r1[d] = __ldg(&Wu1[d*64 + 32 + lane]);
    w2A[d]  = __ldg(&Wu2[d*32 + lane]);
    w2B[d]  = __ldg(&Wu2[(32+d)*32 + lane]);
  }

  if (lane < KNN) sSrc[w][lane] = g_src[i*KNN + lane];
  __syncwarp();

  float pda = g_pd[i*64 + lane];
  float pdb = g_pd[i*64 + 32 + lane];

  for (int c0 = 0; c0 < KNN; c0 += CHK){
    float efv[CHK];
    float2 psv[CHK];
    #pragma unroll
    for (int k = 0; k < CHK; k++){
      efv[k] = g_ef[((size_t)(i*KNN + c0 + k))*EFD + lane];
      psv[k] = g_psp[sSrc[w][c0+k]*32 + lane];
    }
    #pragma unroll
    for (int k = 0; k < CHK; k++) sE[w][k][lane] = efv[k];
    __syncwarp();
    #pragma unroll
    for (int k = 0; k < CHK; k++){
      float y0 = pda + psv[k].x;
      float y1 = pdb + psv[k].y;
      #pragma unroll
      for (int d4 = 0; d4 < 8; d4++){
        float4 a = *(const float4*)&sE[w][k][d4*4];
        y0 = fmaf(a.x, u1r0[d4*4+0], y0); y0 = fmaf(a.y, u1r0[d4*4+1], y0);
        y0 = fmaf(a.z, u1r0[d4*4+2], y0); y0 = fmaf(a.w, u1r0[d4*4+3], y0);
        y1 = fmaf(a.x, u1r1[d4*4+0], y1); y1 = fmaf(a.y, u1r1[d4*4+1], y1);
        y1 = fmaf(a.z, u1r1[d4*4+2], y1); y1 = fmaf(a.w, u1r1[d4*4+3], y1);
      }
      sY[w][k][lane]      = fmaxf(y0, 0.f);
      sY[w][k][32 + lane] = fmaxf(y1, 0.f);
    }
    __syncwarp();
    #pragma unroll
    for (int k = 0; k < CHK; k++){
      float oA = 0.f, oB = 0.f;
      #pragma unroll
      for (int h4 = 0; h4 < 8; h4++){
        float4 a = *(const float4*)&sY[w][k][h4*4];
        oA = fmaf(a.x, w2A[h4*4+0], oA); oB = fmaf(a.y, w2A[h4*4+1], oB);
        oA = fmaf(a.z, w2A[h4*4+2], oA); oB = fmaf(a.w, w2A[h4*4+3], oB);
      }
      #pragma unroll
      for (int h4 = 0; h4 < 8; h4++){
        float4 a = *(const float4*)&sY[w][k][32 + h4*4];
        oA = fmaf(a.x, w2B[h4*4+0], oA); oB = fmaf(a.y, w2B[h4*4+1], oB);
        oA = fmaf(a.z, w2B[h4*4+2], oA); oB = fmaf(a.w, w2B[h4*4+3], oB);
      }
      g_ef[((size_t)(i*KNN + c0 + k))*EFD + lane] = efv[k] + oA + oB;
    }
    __syncwarp();
  }
}

// ---------------- LAST phase1 + decode fused (reads slot 1) ----------------
__global__ __launch_bounds__(128) void mp_last_decode(int bufIn,
    const float* __restrict__ We1, const float* __restrict__ We2,
    const float* __restrict__ W0,
    const float* __restrict__ rot,
    const float* __restrict__ Wp0, const float* __restrict__ Wt, const float* __restrict__ bt,
    const float* __restrict__ Wseq1, const float* __restrict__ bseq1,
    const float* __restrict__ Wseq2, const float* __restrict__ bseq2,
    const float* __restrict__ Wseq3, const float* __restrict__ bseq3,
    const float* __restrict__ lit_pos, const float* __restrict__ Wchi, const float* __restrict__ Wpsi,
    float* __restrict__ out)
{
  __shared__ __align__(16) float sE[P1W][CHK][32];
  __shared__ __align__(16) float sT[P1W][CHK][32];
  __shared__ float su[P1W][162];
  __shared__ int sSrc[P1W][32];

  int lane = threadIdx.x & 31;
  int w = threadIdx.x >> 5;
  int i = blockIdx.x*P1W + w;
  if (i >= NRES) return;

  float w1r[32], w2r[32];
  #pragma unroll
  for (int d = 0; d < 32; d++){
    w1r[d] = __ldg(&We1[d*32 + lane]);
    w2r[d] = __ldg(&We2[d*32 + lane]);
  }

  if (lane < KNN) sSrc[w][lane] = g_src[i*KNN + lane];
  __syncwarp();

  const float* h0in = g_h0[bufIn];
  const float* hsIn = g_hsS[1];

  float h0d = h0in[i*HDIM + lane];
  float hd  = g_hdS[1][i*HDIM + lane];
  float acc0 = 0.f;

  for (int c0 = 0; c0 < KNN; c0 += CHK){
    float efv[CHK], hsv[CHK], h0v[CHK];
    #pragma unroll
    for (int k = 0; k < CHK; k++){
      int s = sSrc[w][c0 + k];
      hsv[k] = hsIn[s*HDIM + lane];
      h0v[k] = h0in[s*HDIM + lane];
      efv[k] = g_ef[((size_t)(i*KNN + c0 + k))*EFD + lane];
    }
    #pragma unroll
    for (int k = 0; k < CHK; k++) sE[w][k][lane] = efv[k];
    __syncwarp();
    #pragma unroll
    for (int k = 0; k < CHK; k++){
      float t0 = hd + hsv[k];
      float t1 = 0.f;
      #pragma unroll
      for (int d4 = 0; d4 < 8; d4++){
        float4 a = *(const float4*)&sE[w][k][d4*4];
        t0 = fmaf(a.x, w1r[d4*4+0], t0); t1 = fmaf(a.y, w1r[d4*4+1], t1);
        t0 = fmaf(a.z, w1r[d4*4+2], t0); t1 = fmaf(a.w, w1r[d4*4+3], t1);
      }
      sT[w][k][lane] = fmaxf(t0 + t1, 0.f);
    }
    __syncwarp();
    #pragma unroll
    for (int k = 0; k < CHK; k++){
      float g0 = 0.f, g1 = 0.f;
      #pragma unroll
      for (int d4 = 0; d4 < 8; d4++){
        float4 a = *(const float4*)&sT[w][k][d4*4];
        g0 = fmaf(a.x, w2r[d4*4+0], g0); g1 = fmaf(a.y, w2r[d4*4+1], g1);
        g0 = fmaf(a.z, w2r[d4*4+2], g0); g1 = fmaf(a.w, w2r[d4*4+3], g1);
      }
      acc0 = fmaf(g0 + g1, h0v[k], acc0);
    }
    __syncwarp();
  }

  acc0 *= 1.f/(float)KNN;
  float u0 = 0.f, u1 = 0.f;
  #pragma unroll
  for (int d = 0; d < 32; d += 2){
    u0 = fmaf(__shfl_sync(0xffffffffu, acc0, d),   __ldg(&W0[d*32+lane]),     u0);
    u1 = fmaf(__shfl_sync(0xffffffffu, acc0, d+1), __ldg(&W0[(d+1)*32+lane]), u1);
  }
  float h0c = h0d + fmaxf(u0 + u1, 0.f);

  // ---- decode (identical numerics) ----
  float t0 = 0.f;
  #pragma unroll
  for (int d = 0; d < 32; d++) t0 = fmaf(__shfl_sync(0xffffffffu, h0c, d), Wp0[d*32 + lane], t0);
  t0 = fmaxf(t0, 0.f);
  #pragma unroll
  for (int r = 0; r < 6; r++){
    int idx = r*32 + lane;
    int widx = idx < 162 ? idx : 161;
    float u = bt[widx];
    #pragma unroll
    for (int c = 0; c < 32; c++) u = fmaf(__shfl_sync(0xffffffffu, t0, c), Wt[c*162 + widx], u);
    if (idx < 162) su[w][idx] = u;
  }
  __syncwarp();
  for (int j = lane; j < 81; j += 32){
    float a = su[w][2*j], b = su[w][2*j+1];
    float ea = a + 1e-8f, eb = b + 1e-8f;
    float den = sqrtf(ea*ea + eb*eb);
    su[w][2*j]   = a / den;
    su[w][2*j+1] = b / den;
  }
  __syncwarp();
  float p0 = su[w][0], p1 = su[w][1];
  float r00=rot[i*9+0], r01=rot[i*9+1], r02=rot[i*9+2];
  float r10=rot[i*9+3], r11=rot[i*9+4], r12=rot[i*9+5];
  float r20=rot[i*9+6], r21=rot[i*9+7], r22=rot[i*9+8];

  for (int m = lane; m < 91; m += 32){
    int k, a;
    if (m < 4){ k = 0; a = m; }
    else { k = c_aa[m-4]; a = 4 + c_off[m-4]; }
    float chi[8];
    #pragma unroll
    for (int t = 0; t < 4; t++){
      chi[2*t]   = su[w][2*(1 + k*4 + t)];
      chi[2*t+1] = su[w][2*(1 + k*4 + t) + 1];
    }
    float l[3];
    #pragma unroll
    for (int j = 0; j < 3; j++){
      float acc = lit_pos[(k*14 + a)*3 + j];
      #pragma unroll
      for (int c = 0; c < 8; c++) acc = fmaf(chi[c], Wchi[(c*14 + a)*3 + j], acc);
      acc = fmaf(p0, Wpsi[(0*14 + a)*3 + j], acc);
      acc = fmaf(p1, Wpsi[(1*14 + a)*3 + j], acc);
      l[j] = acc;
    }
    out[((size_t)i*91 + m)*3 + 0] = r00*l[0] + r01*l[1] + r02*l[2];
    out[((size_t)i*91 + m)*3 + 1] = r10*l[0] + r11*l[1] + r12*l[2];
    out[((size_t)i*91 + m)*3 + 2] = r20*l[0] + r21*l[1] + r22*l[2];
  }

  float s1a = bseq1[lane], s1b = bseq1[32 + lane];
  #pragma unroll
  for (int d = 0; d < 32; d++){
    float h = __shfl_sync(0xffffffffu, h0c, d);
    s1a = fmaf(h, Wseq1[d*64 + lane],      s1a);
    s1b = fmaf(h, Wseq1[d*64 + 32 + lane], s1b);
  }
  s1a = fmaxf(s1a, 0.f); s1b = fmaxf(s1b, 0.f);
  float s2 = bseq2[lane];
  #pragma unroll
  for (int h = 0; h < 32; h++) s2 = fmaf(__shfl_sync(0xffffffffu, s1a, h), Wseq2[h*32 + lane], s2);
  #pragma unroll
  for (int h = 0; h < 32; h++) s2 = fmaf(__shfl_sync(0xffffffffu, s1b, h), Wseq2[(32+h)*32 + lane], s2);
  s2 = fmaxf(s2, 0.f);
  int ll = lane < 20 ? lane : 19;
  float lg = bseq3[ll];
  #pragma unroll
  for (int c = 0; c < 32; c++) lg = fmaf(__shfl_sync(0xffffffffu, s2, c), Wseq3[c*20 + ll], lg);
  float mv = (lane < 20) ? lg : -3.0e38f;
  #pragma unroll
  for (int o = 16; o > 0; o >>= 1) mv = fmaxf(mv, __shfl_xor_sync(0xffffffffu, mv, o));
  float ex = (lane < 20) ? expf(lg - mv) : 0.f;
  #pragma unroll
  for (int o = 16; o > 0; o >>= 1) ex += __shfl_xor_sync(0xffffffffu, ex, o);
  if (lane < 20) out[(size_t)NRES*273 + (size_t)i*20 + lane] = lg - mv - logf(ex);
}

// ---------------- launch ----------------
extern "C" void kernel_launch(void* const* d_in, const int* in_sizes, int n_in,
                              void* d_out, int out_size)
{
  const float* bb      = (const float*)d_in[0];
  const float* latent  = (const float*)d_in[1];
  const float* rrot    = (const float*)d_in[2];
  const float* rtrans  = (const float*)d_in[3];
  const float* Wemb0   = (const float*)d_in[4];
  const float* Wemb1   = (const float*)d_in[5];
  const float* We1s    = (const float*)d_in[6];
  const float* Wss     = (const float*)d_in[7];
  const float* Wds     = (const float*)d_in[8];
  const float* We2s    = (const float*)d_in[9];
  const float* Wvs     = (const float*)d_in[10];
  const float* W0s     = (const float*)d_in[11];
  const float* W1s     = (const float*)d_in[12];
  const float* Wu1s    = (const float*)d_in[13];
  const float* Wu2s    = (const float*)d_in[14];
  const float* Wp0     = (const float*)d_in[15];
  const float* Wt      = (const float*)d_in[16];
  const float* bt      = (const float*)d_in[17];
  const float* Wseq1   = (const float*)d_in[18];
  const float* bseq1   = (const float*)d_in[19];
  const float* Wseq2   = (const float*)d_in[20];
  const float* bseq2   = (const float*)d_in[21];
  const float* Wseq3   = (const float*)d_in[22];
  const float* bseq3   = (const float*)d_in[23];
  const float* lit_pos = (const float*)d_in[24];
  const float* Wchi    = (const float*)d_in[25];
  const float* Wpsi    = (const float*)d_in[26];
  const int*   bids    = (const int*)d_in[28];
  float* out = (float*)d_out;

  const int GP = (NRES + P1W - 1) / P1W;   // 2500

  init_ranges_kernel<<<1, 32>>>();
  batch_range_kernel<<<(NRES+255)/256, 256>>>(bids);
  node_embed_kernel<<<1250, 256>>>(bb, latent, Wemb0, Wemb1, Wss, Wds, Wvs);
  knn_kernel<<<1250, 256>>>(bids);

  // layer 0: buf0 -> buf1; reads slot0, writes slot1 precomputes
  mp_phase1<true,true><<<GP, 128>>>(0, 0, We1s, We2s, W0s, W1s, Wu1s,
      Wss + 1024, Wds + 1024, Wvs + 1024);
  mp_phase2<<<GP, 128>>>(Wu1s, Wu2s);

  // layer 1: buf1 -> buf0; reads slot1, writes slot0
  mp_phase1<false,true><<<GP, 128>>>(1, 1,
      We1s + 1024, We2s + 1024, W0s + 1024, W1s + 1024, Wu1s + 6144,
      Wss + 2048, Wds + 2048, Wvs + 2048);
  mp_phase2<<<GP, 128>>>(Wu1s + 6144, Wu2s + 2048);

  // layer 2: buf0 -> buf1; reads slot0, writes slot1 (no hv for last layer)
  mp_phase1<false,false><<<GP, 128>>>(0, 0,
      We1s + 2048, We2s + 2048, W0s + 2048, W1s + 2048, Wu1s + 2*6144,
      Wss + 3072, Wds + 3072, Wvs + 3072);
  mp_phase2<<<GP, 128>>>(Wu1s + 2*6144, Wu2s + 2*2048);

  // layer 3 (LAST) fused with decode: reads buf1 + slot1
  mp_last_decode<<<GP, 128>>>(1,
      We1s + 3072, We2s + 3072, W0s + 3072,
      rrot, Wp0, Wt, bt,
      Wseq1, bseq1, Wseq2, bseq2, Wseq3, bseq3,
      lit_pos, Wchi, Wpsi, out);
}

// round 17
// speedup vs baseline: 1.0489x; 1.0118x over previous
#include <cuda_runtime.h>
#include <math.h>

#define NRES 10000
#define KNN 30
#define HDIM 32
#define EFD 32
#define NEDGE (NRES*KNN)

// ---------------- device scratch ----------------
__device__ float g_h0[2][NRES*HDIM];
__device__ float g_h1[2][NRES*3*HDIM];
__device__ float g_ef[NEDGE*EFD];
__device__ int   g_src[NEDGE];
__device__ float4 g_xca4[NRES];
__device__ int   g_bstart[8];
__device__ int   g_bend[8];
// parity-slotted (writer = phase1(l) epilogue -> slot (l+1)&1; reader = phase1(l+1))
__device__ float g_hsS[2][NRES*HDIM];
__device__ float g_hdS[2][NRES*HDIM];
__device__ float g_hvS[2][3*NRES*HDIM];   // plane-major within slot
// produced by phase1(l), consumed by phase2(l)
__device__ float2 g_psp[NRES*HDIM];       // (psa,psb) per (node,lane)
__device__ float  g_pd[NRES*64];

__constant__ int c_aa[87] = {
  0,
  1,1,1,1,1,1,1, 2,2,2,2, 3,3,3,3, 4,4, 5,5,5,5,5, 6,6,6,6,6,
  8,8,8,8,8,8, 9,9,9,9, 10,10,10,10, 11,11,11,11,11, 12,12,12,12,
  13,13,13,13,13,13,13, 14,14,14, 15,15, 16,16,16,
  17,17,17,17,17,17,17,17,17,17, 18,18,18,18,18,18,18,18, 19,19,19
};
__constant__ int c_off[87] = {
  0,
  0,1,2,3,4,5,6, 0,1,2,3, 0,1,2,3, 0,1, 0,1,2,3,4, 0,1,2,3,4,
  0,1,2,3,4,5, 0,1,2,3, 0,1,2,3, 0,1,2,3,4, 0,1,2,3,
  0,1,2,3,4,5,6, 0,1,2, 0,1, 0,1,2,
  0,1,2,3,4,5,6,7,8,9, 0,1,2,3,4,5,6,7, 0,1,2
};

__device__ __forceinline__ float fin0(float v){ return isfinite(v) ? v : 0.f; }

// ---------------- node features + embeddings + layer-0 precompute (slot 0)
//                  + batch-range boundary detection (bids sorted => no atomics) ----------------
__global__ __launch_bounds__(256) void node_embed_kernel(
    const float* __restrict__ bb, const float* __restrict__ lat,
    const float* __restrict__ Wemb0, const float* __restrict__ Wemb1,
    const float* __restrict__ Wss0, const float* __restrict__ Wds0,
    const float* __restrict__ Wvs0, const int* __restrict__ bid)
{
  int lane = threadIdx.x & 31;
  int i = blockIdx.x*8 + (threadIdx.x >> 5);
  if (i >= NRES) return;

  float ca0 = bb[i*12+3], ca1 = bb[i*12+4], ca2 = bb[i*12+5];
  if (lane == 0){
    g_xca4[i] = make_float4(ca0, ca1, ca2, ca0*ca0 + ca1*ca1 + ca2*ca2);
    int b = bid[i];
    if (i == 0        || bid[i-1] != b) g_bstart[b] = i;
    if (i == NRES-1   || bid[i+1] != b) g_bend[b]   = i+1;
  }

  float Dv[3];
  #pragma unroll
  for (int t3 = 0; t3 < 3; t3++){
    int t = 3*i + t3;
    float D = 0.f;
    if (t >= 1 && t <= 3*NRES - 3){
      int d0 = t - 1;
      float x[4][3];
      #pragma unroll
      for (int q = 0; q < 4; q++){
        int m = d0 + q; int r = m/3; int am = m - r*3;
        x[q][0] = bb[r*12 + am*3 + 0];
        x[q][1] = bb[r*12 + am*3 + 1];
        x[q][2] = bb[r*12 + am*3 + 2];
      }
      float u2[3], u1[3], u0[3];
      #pragma unroll
      for (int c = 0; c < 3; c++){ u2[c]=x[1][c]-x[0][c]; u1[c]=x[2][c]-x[1][c]; u0[c]=x[3][c]-x[2][c]; }
      float n2n = sqrtf(u2[0]*u2[0]+u2[1]*u2[1]+u2[2]*u2[2]) + 1e-8f;
      float n1n = sqrtf(u1[0]*u1[0]+u1[1]*u1[1]+u1[2]*u1[2]) + 1e-8f;
      float n0n = sqrtf(u0[0]*u0[0]+u0[1]*u0[1]+u0[2]*u0[2]) + 1e-8f;
      #pragma unroll
      for (int c = 0; c < 3; c++){ u2[c]/=n2n; u1[c]/=n1n; u0[c]/=n0n; }
      float c21[3] = { u2[1]*u1[2]-u2[2]*u1[1], u2[2]*u1[0]-u2[0]*u1[2], u2[0]*u1[1]-u2[1]*u1[0] };
      float c10[3] = { u1[1]*u0[2]-u1[2]*u0[1], u1[2]*u0[0]-u1[0]*u0[2], u1[0]*u0[1]-u1[1]*u0[0] };
      float l21 = sqrtf(c21[0]*c21[0]+c21[1]*c21[1]+c21[2]*c21[2]) + 1e-8f;
      float l10 = sqrtf(c10[0]*c10[0]+c10[1]*c10[1]+c10[2]*c10[2]) + 1e-8f;
      #pragma unroll
      for (int c = 0; c < 3; c++){ c21[c]/=l21; c10[c]/=l10; }
      float cosD = c21[0]*c10[0]+c21[1]*c10[1]+c21[2]*c10[2];
      cosD = fminf(fmaxf(cosD, -1.f + 1e-7f), 1.f - 1e-7f);
      float sdot = u2[0]*c10[0]+u2[1]*c10[1]+u2[2]*c10[2];
      float sgn = (sdot > 0.f) ? 1.f : ((sdot < 0.f) ? -1.f : 0.f);
      D = sgn * acosf(cosD);
    }
    Dv[t3] = D;
  }
  float x0[7] = { cosf(Dv[0]), cosf(Dv[1]), cosf(Dv[2]),
                  sinf(Dv[0]), sinf(Dv[1]), sinf(Dv[2]), 1.f };

  float v[7][3];
  #pragma unroll
  for (int a = 0; a < 4; a++){
    v[a][0] = bb[i*12 + a*3 + 0] - ca0;
    v[a][1] = bb[i*12 + a*3 + 1] - ca1;
    v[a][2] = bb[i*12 + a*3 + 2] - ca2;
  }
  if (i < NRES-1){
    float dx = bb[(i+1)*12+3] - ca0, dy = bb[(i+1)*12+4] - ca1, dz = bb[(i+1)*12+5] - ca2;
    float n = sqrtf(dx*dx+dy*dy+dz*dz) + 1e-8f;
    v[4][0]=dx/n; v[4][1]=dy/n; v[4][2]=dz/n;
  } else { v[4][0]=v[4][1]=v[4][2]=0.f; }
  if (i > 0){
    float dx = ca0 - bb[(i-1)*12+3], dy = ca1 - bb[(i-1)*12+4], dz = ca2 - bb[(i-1)*12+5];
    float n = sqrtf(dx*dx+dy*dy+dz*dz) + 1e-8f;
    v[5][0]=-dx/n; v[5][1]=-dy/n; v[5][2]=-dz/n;
  } else { v[5][0]=v[5][1]=v[5][2]=0.f; }
  {
    float b0 = ca0 - bb[i*12+0], b1 = ca1 - bb[i*12+1], b2 = ca2 - bb[i*12+2];
    float cc0 = bb[i*12+6] - ca0, cc1 = bb[i*12+7] - ca1, cc2 = bb[i*12+8] - ca2;
    float a0 = b1*cc2 - b2*cc1, a1 = b2*cc0 - b0*cc2, a2 = b0*cc1 - b1*cc0;
    v[6][0] = -0.58273431f*a0 + 0.56802827f*b0 - 0.54067466f*cc0;
    v[6][1] = -0.58273431f*a1 + 0.56802827f*b1 - 0.54067466f*cc1;
    v[6][2] = -0.58273431f*a2 + 0.56802827f*b2 - 0.54067466f*cc2;
  }
  #pragma unroll
  for (int q = 0; q < 7; q++){
    v[q][0]=fin0(v[q][0]); v[q][1]=fin0(v[q][1]); v[q][2]=fin0(v[q][2]);
  }

  float acc = 0.f;
  #pragma unroll
  for (int d = 0; d < 7; d++) acc = fmaf(x0[d], Wemb0[d*32 + lane], acc);
  for (int d = 0; d < 32; d++) acc = fmaf(lat[(i*4+0)*32 + d], Wemb0[(7+d)*32 + lane], acc);
  float h0r = fmaxf(acc, 0.f);
  g_h0[0][i*32 + lane] = h0r;

  float h1r[3];
  #pragma unroll
  for (int j = 0; j < 3; j++){
    float a2 = 0.f;
    #pragma unroll
    for (int d = 0; d < 7; d++) a2 = fmaf(v[d][j], Wemb1[d*32 + lane], a2);
    for (int d = 0; d < 32; d++) a2 = fmaf(lat[(i*4+1+j)*32 + d], Wemb1[(7+d)*32 + lane], a2);
    h1r[j] = a2;
    g_h1[0][(i*3+j)*32 + lane] = a2;
  }

  float hs = 0.f, hdv = 0.f;
  #pragma unroll
  for (int d = 0; d < 32; d++){
    float a = __shfl_sync(0xffffffffu, h0r, d);
    hs  = fmaf(a, __ldg(&Wss0[d*32+lane]), hs);
    hdv = fmaf(a, __ldg(&Wds0[d*32+lane]), hdv);
  }
  g_hsS[0][i*32+lane] = hs;
  g_hdS[0][i*32+lane] = hdv;
  #pragma unroll
  for (int c = 0; c < 3; c++){
    float hv = 0.f;
    #pragma unroll
    for (int d = 0; d < 32; d++)
      hv = fmaf(__shfl_sync(0xffffffffu, h1r[c], d), __ldg(&Wvs0[d*32+lane]), hv);
    g_hvS[0][c*NRES*32 + i*32 + lane] = hv;
  }
}

// ---------------- kNN: hybrid bitonic / serial-insertion top-32 ----------------
__device__ __forceinline__ unsigned long long shfx64(unsigned long long v, int m){
  return __shfl_xor_sync(0xffffffffu, v, m);
}

__global__ __launch_bounds__(256) void knn_kernel(const int* __restrict__ bid){
  int lane = threadIdx.x & 31;
  int i = blockIdx.x*8 + (threadIdx.x >> 5);
  if (i >= NRES) return;
  float4 qi = g_xca4[i];
  int b = bid[i];
  int lo = g_bstart[b], hi = g_bend[b];

  const unsigned long long INF = 0xFFFFFFFFFFFFFFFFull;
  unsigned long long state = INF;
  unsigned long long worst = INF;

  for (int j0 = lo; j0 < hi; j0 += 32){
    int j = j0 + lane;
    unsigned long long key = INF;
    if (j < hi && j != i){
      float4 qj = g_xca4[j];
      float d2 = fmaf(-2.f, qi.x*qj.x + qi.y*qj.y + qi.z*qj.z, qi.w + qj.w);
      unsigned int fb = __float_as_uint(d2);
      fb = (fb & 0x80000000u) ? ~fb : (fb | 0x80000000u);
      key = ((unsigned long long)fb << 32) | (unsigned int)j;
    }
    unsigned int qual = __ballot_sync(0xffffffffu, key < worst);
    if (!qual) continue;

    if (__popc(qual) >= 12){
      #pragma unroll
      for (int k = 2; k <= 32; k <<= 1){
        #pragma unroll
        for (int jj = k >> 1; jj > 0; jj >>= 1){
          unsigned long long o = shfx64(key, jj);
          bool up = ((lane & k) == 0);
          bool lower = ((lane & jj) == 0);
          bool keepmin = (up == lower);
          key = ((o < key) == keepmin) ? o : key;
        }
      }
      unsigned long long rev = shfx64(key, 31);
      unsigned long long m = (rev < state) ? rev : state;
      #pragma unroll
      for (int jj = 16; jj > 0; jj >>= 1){
        unsigned long long o = shfx64(m, jj);
        bool lower = ((lane & jj) == 0);
        m = ((o < m) == lower) ? o : m;
      }
      state = m;
      worst = __shfl_sync(0xffffffffu, state, 31);
    } else {
      while (qual){
        int src = __ffs(qual) - 1;
        qual &= qual - 1;
        unsigned long long x = __shfl_sync(0xffffffffu, key, src);
        unsigned int gmask = __ballot_sync(0xffffffffu, state > x);
        if (!gmask) continue;
        int pos = __ffs(gmask) - 1;
        unsigned long long up = __shfl_up_sync(0xffffffffu, state, 1);
        state = (lane < pos) ? state : ((lane == pos) ? x : up);
      }
      worst = __shfl_sync(0xffffffffu, state, 31);
    }
  }

  if (lane < KNN){
    g_src[i*KNN + lane] = (state == INF) ? i : (int)(unsigned int)(state & 0xFFFFFFFFull);
  }
}

// ---------------- phase 1 (layers 0..2): register weights, batched gathers ----------------
// Reads slot slotIn; epilogue writes ps/pd + hs/hd (+hv if DOHVN) to slot slotIn^1.
#define CHK 6
#define P1W 4
template<bool FIRST, bool DOHVN>
__global__ __launch_bounds__(128) void mp_phase1(int bufIn, int slotIn,
    const float* __restrict__ We1, const float* __restrict__ We2,
    const float* __restrict__ W0,  const float* __restrict__ W1,
    const float* __restrict__ Wu1,
    const float* __restrict__ Wssn, const float* __restrict__ Wdsn,
    const float* __restrict__ Wvsn)
{
  __shared__ __align__(16) float sE[P1W][CHK][32];
  __shared__ __align__(16) float sT[P1W][CHK][32];
  __shared__ int sSrc[P1W][32];

  int lane = threadIdx.x & 31;
  int w = threadIdx.x >> 5;
  int i = blockIdx.x*P1W + w;
  if (i >= NRES) return;
  int slotN = slotIn ^ 1;

  float w1r[32], w2r[32];
  #pragma unroll
  for (int d = 0; d < 32; d++){
    w1r[d] = __ldg(&We1[d*32 + lane]);
    w2r[d] = __ldg(&We2[d*32 + lane]);
  }

  if (lane < KNN) sSrc[w][lane] = g_src[i*KNN + lane];
  __syncwarp();

  float4 qi = make_float4(0.f,0.f,0.f,0.f);
  float mu = 0.f, fr = 0.f;
  if (FIRST){
    qi = g_xca4[i];
    if (lane < 16) mu = (float)lane * (20.f/15.f);
    else fr = expf(-((float)(2*((lane-16)&7))/16.f) * 9.210340371976184f);
  }

  const float* h0in = g_h0[bufIn];  float* h0out = g_h0[bufIn^1];
  const float* h1in = g_h1[bufIn];  float* h1out = g_h1[bufIn^1];
  const float* hsIn = g_hsS[slotIn];
  const float* hvIn = g_hvS[slotIn];

  float h0d = h0in[i*HDIM + lane];
  float hd  = g_hdS[slotIn][i*HDIM + lane];
  float acc0 = 0.f, av0 = 0.f, av1 = 0.f, av2 = 0.f;

  for (int c0 = 0; c0 < KNN; c0 += CHK){
    float efv[CHK], hsv[CHK], h0v[CHK];
    #pragma unroll
    for (int k = 0; k < CHK; k++){
      int s = sSrc[w][c0 + k];
      hsv[k] = hsIn[s*HDIM + lane];
      h0v[k] = h0in[s*HDIM + lane];
      if (FIRST){
        float4 qs = g_xca4[s];
        float dx = qi.x-qs.x, dy = qi.y-qs.y, dz = qi.z-qs.z;
        float dist = sqrtf(dx*dx + dy*dy + dz*dz);
        float val;
        if (lane < 16){ float t = (dist - mu) / 1.25f; val = expf(-t*t); }
        else { float a = (float)(s - i) * fr; val = (lane < 24) ? cosf(a) : sinf(a); }
        efv[k] = val;
        g_ef[((size_t)(i*KNN + c0 + k))*EFD + lane] = val;
      } else {
        efv[k] = g_ef[((size_t)(i*KNN + c0 + k))*EFD + lane];
      }
    }
    #pragma unroll
    for (int k = 0; k < CHK; k++) sE[w][k][lane] = efv[k];
    __syncwarp();
    #pragma unroll
    for (int k = 0; k < CHK; k++){
      float t0 = hd + hsv[k];
      float t1 = 0.f;
      #pragma unroll
      for (int d4 = 0; d4 < 8; d4++){
        float4 a = *(const float4*)&sE[w][k][d4*4];
        t0 = fmaf(a.x, w1r[d4*4+0], t0); t1 = fmaf(a.y, w1r[d4*4+1], t1);
        t0 = fmaf(a.z, w1r[d4*4+2], t0); t1 = fmaf(a.w, w1r[d4*4+3], t1);
      }
      sT[w][k][lane] = fmaxf(t0 + t1, 0.f);
    }
    __syncwarp();
    float gk[CHK];
    #pragma unroll
    for (int k = 0; k < CHK; k++){
      float g0 = 0.f, g1 = 0.f;
      #pragma unroll
      for (int d4 = 0; d4 < 8; d4++){
        float4 a = *(const float4*)&sT[w][k][d4*4];
        g0 = fmaf(a.x, w2r[d4*4+0], g0); g1 = fmaf(a.y, w2r[d4*4+1], g1);
        g0 = fmaf(a.z, w2r[d4*4+2], g0); g1 = fmaf(a.w, w2r[d4*4+3], g1);
      }
      gk[k] = g0 + g1;
    }
    #pragma unroll
    for (int k = 0; k < CHK; k++) acc0 = fmaf(gk[k], h0v[k], acc0);
    {
      float hvv[CHK];
      #pragma unroll
      for (int k = 0; k < CHK; k++) hvv[k] = hvIn[0*NRES*32 + sSrc[w][c0+k]*32 + lane];
      #pragma unroll
      for (int k = 0; k < CHK; k++) av0 = fmaf(gk[k], hvv[k], av0);
      #pragma unroll
      for (int k = 0; k < CHK; k++) hvv[k] = hvIn[1*NRES*32 + sSrc[w][c0+k]*32 + lane];
      #pragma unroll
      for (int k = 0; k < CHK; k++) av1 = fmaf(gk[k], hvv[k], av1);
      #pragma unroll
      for (int k = 0; k < CHK; k++) hvv[k] = hvIn[2*NRES*32 + sSrc[w][c0+k]*32 + lane];
      #pragma unroll
      for (int k = 0; k < CHK; k++) av2 = fmaf(gk[k], hvv[k], av2);
    }
    __syncwarp();
  }

  const float inv = 1.f/(float)KNN;
  acc0 *= inv;

  float u0 = 0.f, u1 = 0.f;
  #pragma unroll
  for (int d = 0; d < 32; d += 2){
    u0 = fmaf(__shfl_sync(0xffffffffu, acc0, d),   __ldg(&W0[d*32+lane]),     u0);
    u1 = fmaf(__shfl_sync(0xffffffffu, acc0, d+1), __ldg(&W0[(d+1)*32+lane]), u1);
  }
  float h0new = h0d + fmaxf(u0 + u1, 0.f);
  h0out[i*HDIM + lane] = h0new;

  av0 *= inv; av1 *= inv; av2 *= inv;
  float o0 = 0.f, o1 = 0.f, o2 = 0.f;
  #pragma unroll
  for (int d = 0; d < 32; d++){
    float wv = __ldg(&W1[d*32+lane]);
    o0 = fmaf(__shfl_sync(0xffffffffu, av0, d), wv, o0);
    o1 = fmaf(__shfl_sync(0xffffffffu, av1, d), wv, o1);
    o2 = fmaf(__shfl_sync(0xffffffffu, av2, d), wv, o2);
  }
  float h1n0 = h1in[(i*3+0)*HDIM + lane] + o0;
  float h1n1 = h1in[(i*3+1)*HDIM + lane] + o1;
  float h1n2 = h1in[(i*3+2)*HDIM + lane] + o2;
  h1out[(i*3+0)*HDIM + lane] = h1n0;
  h1out[(i*3+1)*HDIM + lane] = h1n1;
  h1out[(i*3+2)*HDIM + lane] = h1n2;

  // ps/pd for phase2(l)
  const float* U1b = Wu1 + 2048;
  const float* U1c = Wu1 + 4096;
  float psa = 0.f, psb = 0.f, pda = 0.f, pdb = 0.f;
  #pragma unroll
  for (int d = 0; d < 32; d++){
    float h = __shfl_sync(0xffffffffu, h0new, d);
    psa = fmaf(h, __ldg(&U1b[d*64 + lane]),      psa);
    psb = fmaf(h, __ldg(&U1b[d*64 + 32 + lane]), psb);
    pda = fmaf(h, __ldg(&U1c[d*64 + lane]),      pda);
    pdb = fmaf(h, __ldg(&U1c[d*64 + 32 + lane]), pdb);
  }
  g_psp[i*32 + lane] = make_float2(psa, psb);
  g_pd[i*64 + lane]      = pda;
  g_pd[i*64 + 32 + lane] = pdb;

  // next-layer hs/hd (+hv) -> slot slotN (activations hot in registers)
  float hsn = 0.f, hdn = 0.f;
  #pragma unroll
  for (int d = 0; d < 32; d++){
    float a = __shfl_sync(0xffffffffu, h0new, d);
    hsn = fmaf(a, __ldg(&Wssn[d*32+lane]), hsn);
    hdn = fmaf(a, __ldg(&Wdsn[d*32+lane]), hdn);
  }
  g_hsS[slotN][i*32+lane] = hsn;
  g_hdS[slotN][i*32+lane] = hdn;
  if (DOHVN){
    float hv0 = 0.f, hv1 = 0.f, hv2 = 0.f;
    #pragma unroll
    for (int d = 0; d < 32; d++){
      float wv = __ldg(&Wvsn[d*32+lane]);
      hv0 = fmaf(__shfl_sync(0xffffffffu, h1n0, d), wv, hv0);
      hv1 = fmaf(__shfl_sync(0xffffffffu, h1n1, d), wv, hv1);
      hv2 = fmaf(__shfl_sync(0xffffffffu, h1n2, d), wv, hv2);
    }
    g_hvS[slotN][0*NRES*32 + i*32 + lane] = hv0;
    g_hvS[slotN][1*NRES*32 + i*32 + lane] = hv1;
    g_hvS[slotN][2*NRES*32 + i*32 + lane] = hv2;
  }
}

// ---------------- phase 2 (epilogue-free) ----------------
__global__ __launch_bounds__(128) void mp_phase2(
    const float* __restrict__ Wu1, const float* __restrict__ Wu2)
{
  __shared__ __align__(16) float sE[P1W][CHK][32];
  __shared__ __align__(16) float sY[P1W][CHK][64];
  __shared__ int sSrc[P1W][32];

  int lane = threadIdx.x & 31;
  int w = threadIdx.x >> 5;
  int i = blockIdx.x*P1W + w;
  if (i >= NRES) return;

  float u1r0[32], u1r1[32], w2A[32], w2B[32];
  #pragma unroll
  for (int d = 0; d < 32; d++){
    u1r0[d] = __ldg(&Wu1[d*64 + lane]);
    u1r1[d] = __ldg(&Wu1[d*64 + 32 + lane]);
    w2A[d]  = __ldg(&Wu2[d*32 + lane]);
    w2B[d]  = __ldg(&Wu2[(32+d)*32 + lane]);
  }

  if (lane < KNN) sSrc[w][lane] = g_src[i*KNN + lane];
  __syncwarp();

  float pda = g_pd[i*64 + lane];
  float pdb = g_pd[i*64 + 32 + lane];

  for (int c0 = 0; c0 < KNN; c0 += CHK){
    float efv[CHK];
    float2 psv[CHK];
    #pragma unroll
    for (int k = 0; k < CHK; k++){
      efv[k] = g_ef[((size_t)(i*KNN + c0 + k))*EFD + lane];
      psv[k] = g_psp[sSrc[w][c0+k]*32 + lane];
    }
    #pragma unroll
    for (int k = 0; k < CHK; k++) sE[w][k][lane] = efv[k];
    __syncwarp();
    #pragma unroll
    for (int k = 0; k < CHK; k++){
      float y0 = pda + psv[k].x;
      float y1 = pdb + psv[k].y;
      #pragma unroll
      for (int d4 = 0; d4 < 8; d4++){
        float4 a = *(const float4*)&sE[w][k][d4*4];
        y0 = fmaf(a.x, u1r0[d4*4+0], y0); y0 = fmaf(a.y, u1r0[d4*4+1], y0);
        y0 = fmaf(a.z, u1r0[d4*4+2], y0); y0 = fmaf(a.w, u1r0[d4*4+3], y0);
        y1 = fmaf(a.x, u1r1[d4*4+0], y1); y1 = fmaf(a.y, u1r1[d4*4+1], y1);
        y1 = fmaf(a.z, u1r1[d4*4+2], y1); y1 = fmaf(a.w, u1r1[d4*4+3], y1);
      }
      sY[w][k][lane]      = fmaxf(y0, 0.f);
      sY[w][k][32 + lane] = fmaxf(y1, 0.f);
    }
    __syncwarp();
    #pragma unroll
    for (int k = 0; k < CHK; k++){
      float oA = 0.f, oB = 0.f;
      #pragma unroll
      for (int h4 = 0; h4 < 8; h4++){
        float4 a = *(const float4*)&sY[w][k][h4*4];
        oA = fmaf(a.x, w2A[h4*4+0], oA); oB = fmaf(a.y, w2A[h4*4+1], oB);
        oA = fmaf(a.z, w2A[h4*4+2], oA); oB = fmaf(a.w, w2A[h4*4+3], oB);
      }
      #pragma unroll
      for (int h4 = 0; h4 < 8; h4++){
        float4 a = *(const float4*)&sY[w][k][32 + h4*4];
        oA = fmaf(a.x, w2B[h4*4+0], oA); oB = fmaf(a.y, w2B[h4*4+1], oB);
        oA = fmaf(a.z, w2B[h4*4+2], oA); oB = fmaf(a.w, w2B[h4*4+3], oB);
      }
      g_ef[((size_t)(i*KNN + c0 + k))*EFD + lane] = efv[k] + oA + oB;
    }
    __syncwarp();
  }
}

// ---------------- LAST phase1 + decode fused (reads slot 1) ----------------
__global__ __launch_bounds__(128) void mp_last_decode(int bufIn,
    const float* __restrict__ We1, const float* __restrict__ We2,
    const float* __restrict__ W0,
    const float* __restrict__ rot,
    const float* __restrict__ Wp0, const float* __restrict__ Wt, const float* __restrict__ bt,
    const float* __restrict__ Wseq1, const float* __restrict__ bseq1,
    const float* __restrict__ Wseq2, const float* __restrict__ bseq2,
    const float* __restrict__ Wseq3, const float* __restrict__ bseq3,
    const float* __restrict__ lit_pos, const float* __restrict__ Wchi, const float* __restrict__ Wpsi,
    float* __restrict__ out)
{
  __shared__ __align__(16) float sE[P1W][CHK][32];
  __shared__ __align__(16) float sT[P1W][CHK][32];
  __shared__ float su[P1W][162];
  __shared__ int sSrc[P1W][32];

  int lane = threadIdx.x & 31;
  int w = threadIdx.x >> 5;
  int i = blockIdx.x*P1W + w;
  if (i >= NRES) return;

  float w1r[32], w2r[32];
  #pragma unroll
  for (int d = 0; d < 32; d++){
    w1r[d] = __ldg(&We1[d*32 + lane]);
    w2r[d] = __ldg(&We2[d*32 + lane]);
  }

  if (lane < KNN) sSrc[w][lane] = g_src[i*KNN + lane];
  __syncwarp();

  const float* h0in = g_h0[bufIn];
  const float* hsIn = g_hsS[1];

  float h0d = h0in[i*HDIM + lane];
  float hd  = g_hdS[1][i*HDIM + lane];
  float acc0 = 0.f;

  for (int c0 = 0; c0 < KNN; c0 += CHK){
    float efv[CHK], hsv[CHK], h0v[CHK];
    #pragma unroll
    for (int k = 0; k < CHK; k++){
      int s = sSrc[w][c0 + k];
      hsv[k] = hsIn[s*HDIM + lane];
      h0v[k] = h0in[s*HDIM + lane];
      efv[k] = g_ef[((size_t)(i*KNN + c0 + k))*EFD + lane];
    }
    #pragma unroll
    for (int k = 0; k < CHK; k++) sE[w][k][lane] = efv[k];
    __syncwarp();
    #pragma unroll
    for (int k = 0; k < CHK; k++){
      float t0 = hd + hsv[k];
      float t1 = 0.f;
      #pragma unroll
      for (int d4 = 0; d4 < 8; d4++){
        float4 a = *(const float4*)&sE[w][k][d4*4];
        t0 = fmaf(a.x, w1r[d4*4+0], t0); t1 = fmaf(a.y, w1r[d4*4+1], t1);
        t0 = fmaf(a.z, w1r[d4*4+2], t0); t1 = fmaf(a.w, w1r[d4*4+3], t1);
      }
      sT[w][k][lane] = fmaxf(t0 + t1, 0.f);
    }
    __syncwarp();
    #pragma unroll
    for (int k = 0; k < CHK; k++){
      float g0 = 0.f, g1 = 0.f;
      #pragma unroll
      for (int d4 = 0; d4 < 8; d4++){
        float4 a = *(const float4*)&sT[w][k][d4*4];
        g0 = fmaf(a.x, w2r[d4*4+0], g0); g1 = fmaf(a.y, w2r[d4*4+1], g1);
        g0 = fmaf(a.z, w2r[d4*4+2], g0); g1 = fmaf(a.w, w2r[d4*4+3], g1);
      }
      acc0 = fmaf(g0 + g1, h0v[k], acc0);
    }
    __syncwarp();
  }

  acc0 *= 1.f/(float)KNN;
  float u0 = 0.f, u1 = 0.f;
  #pragma unroll
  for (int d = 0; d < 32; d += 2){
    u0 = fmaf(__shfl_sync(0xffffffffu, acc0, d),   __ldg(&W0[d*32+lane]),     u0);
    u1 = fmaf(__shfl_sync(0xffffffffu, acc0, d+1), __ldg(&W0[(d+1)*32+lane]), u1);
  }
  float h0c = h0d + fmaxf(u0 + u1, 0.f);

  // ---- decode (identical numerics) ----
  float t0 = 0.f;
  #pragma unroll
  for (int d = 0; d < 32; d++) t0 = fmaf(__shfl_sync(0xffffffffu, h0c, d), Wp0[d*32 + lane], t0);
  t0 = fmaxf(t0, 0.f);
  #pragma unroll
  for (int r = 0; r < 6; r++){
    int idx = r*32 + lane;
    int widx = idx < 162 ? idx : 161;
    float u = bt[widx];
    #pragma unroll
    for (int c = 0; c < 32; c++) u = fmaf(__shfl_sync(0xffffffffu, t0, c), Wt[c*162 + widx], u);
    if (idx < 162) su[w][idx] = u;
  }
  __syncwarp();
  for (int j = lane; j < 81; j += 32){
    float a = su[w][2*j], b = su[w][2*j+1];
    float ea = a + 1e-8f, eb = b + 1e-8f;
    float den = sqrtf(ea*ea + eb*eb);
    su[w][2*j]   = a / den;
    su[w][2*j+1] = b / den;
  }
  __syncwarp();
  float p0 = su[w][0], p1 = su[w][1];
  float r00=rot[i*9+0], r01=rot[i*9+1], r02=rot[i*9+2];
  float r10=rot[i*9+3], r11=rot[i*9+4], r12=rot[i*9+5];
  float r20=rot[i*9+6], r21=rot[i*9+7], r22=rot[i*9+8];

  for (int m = lane; m < 91; m += 32){
    int k, a;
    if (m < 4){ k = 0; a = m; }
    else { k = c_aa[m-4]; a = 4 + c_off[m-4]; }
    float chi[8];
    #pragma unroll
    for (int t = 0; t < 4; t++){
      chi[2*t]   = su[w][2*(1 + k*4 + t)];
      chi[2*t+1] = su[w][2*(1 + k*4 + t) + 1];
    }
    float l[3];
    #pragma unroll
    for (int j = 0; j < 3; j++){
      float acc = lit_pos[(k*14 + a)*3 + j];
      #pragma unroll
      for (int c = 0; c < 8; c++) acc = fmaf(chi[c], Wchi[(c*14 + a)*3 + j], acc);
      acc = fmaf(p0, Wpsi[(0*14 + a)*3 + j], acc);
      acc = fmaf(p1, Wpsi[(1*14 + a)*3 + j], acc);
      l[j] = acc;
    }
    out[((size_t)i*91 + m)*3 + 0] = r00*l[0] + r01*l[1] + r02*l[2];
    out[((size_t)i*91 + m)*3 + 1] = r10*l[0] + r11*l[1] + r12*l[2];
    out[((size_t)i*91 + m)*3 + 2] = r20*l[0] + r21*l[1] + r22*l[2];
  }

  float s1a = bseq1[lane], s1b = bseq1[32 + lane];
  #pragma unroll
  for (int d = 0; d < 32; d++){
    float h = __shfl_sync(0xffffffffu, h0c, d);
    s1a = fmaf(h, Wseq1[d*64 + lane],      s1a);
    s1b = fmaf(h, Wseq1[d*64 + 32 + lane], s1b);
  }
  s1a = fmaxf(s1a, 0.f); s1b = fmaxf(s1b, 0.f);
  float s2 = bseq2[lane];
  #pragma unroll
  for (int h = 0; h < 32; h++) s2 = fmaf(__shfl_sync(0xffffffffu, s1a, h), Wseq2[h*32 + lane], s2);
  #pragma unroll
  for (int h = 0; h < 32; h++) s2 = fmaf(__shfl_sync(0xffffffffu, s1b, h), Wseq2[(32+h)*32 + lane], s2);
  s2 = fmaxf(s2, 0.f);
  int ll = lane < 20 ? lane : 19;
  float lg = bseq3[ll];
  #pragma unroll
  for (int c = 0; c < 32; c++) lg = fmaf(__shfl_sync(0xffffffffu, s2, c), Wseq3[c*20 + ll], lg);
  float mv = (lane < 20) ? lg : -3.0e38f;
  #pragma unroll
  for (int o = 16; o > 0; o >>= 1) mv = fmaxf(mv, __shfl_xor_sync(0xffffffffu, mv, o));
  float ex = (lane < 20) ? expf(lg - mv) : 0.f;
  #pragma unroll
  for (int o = 16; o > 0; o >>= 1) ex += __shfl_xor_sync(0xffffffffu, ex, o);
  if (lane < 20) out[(size_t)NRES*273 + (size_t)i*20 + lane] = lg - mv - logf(ex);
}

// ---------------- launch ----------------
extern "C" void kernel_launch(void* const* d_in, const int* in_sizes, int n_in,
                              void* d_out, int out_size)
{
  const float* bb      = (const float*)d_in[0];
  const float* latent  = (const float*)d_in[1];
  const float* rrot    = (const float*)d_in[2];
  const float* rtrans  = (const float*)d_in[3];
  const float* Wemb0   = (const float*)d_in[4];
  const float* Wemb1   = (const float*)d_in[5];
  const float* We1s    = (const float*)d_in[6];
  const float* Wss     = (const float*)d_in[7];
  const float* Wds     = (const float*)d_in[8];
  const float* We2s    = (const float*)d_in[9];
  const float* Wvs     = (const float*)d_in[10];
  const float* W0s     = (const float*)d_in[11];
  const float* W1s     = (const float*)d_in[12];
  const float* Wu1s    = (const float*)d_in[13];
  const float* Wu2s    = (const float*)d_in[14];
  const float* Wp0     = (const float*)d_in[15];
  const float* Wt      = (const float*)d_in[16];
  const float* bt      = (const float*)d_in[17];
  const float* Wseq1   = (const float*)d_in[18];
  const float* bseq1   = (const float*)d_in[19];
  const float* Wseq2   = (const float*)d_in[20];
  const float* bseq2   = (const float*)d_in[21];
  const float* Wseq3   = (const float*)d_in[22];
  const float* bseq3   = (const float*)d_in[23];
  const float* lit_pos = (const float*)d_in[24];
  const float* Wchi    = (const float*)d_in[25];
  const float* Wpsi    = (const float*)d_in[26];
  const int*   bids    = (const int*)d_in[28];
  float* out = (float*)d_out;

  const int GP = (NRES + P1W - 1) / P1W;   // 2500

  // embed computes xca4, h0/h1, layer-0 precomputes AND batch ranges (sorted bids)
  node_embed_kernel<<<1250, 256>>>(bb, latent, Wemb0, Wemb1, Wss, Wds, Wvs, bids);
  knn_kernel<<<1250, 256>>>(bids);

  // layer 0: buf0 -> buf1; reads slot0, writes slot1 precomputes
  mp_phase1<true,true><<<GP, 128>>>(0, 0, We1s, We2s, W0s, W1s, Wu1s,
      Wss + 1024, Wds + 1024, Wvs + 1024);
  mp_phase2<<<GP, 128>>>(Wu1s, Wu2s);

  // layer 1: buf1 -> buf0; reads slot1, writes slot0
  mp_phase1<false,true><<<GP, 128>>>(1, 1,
      We1s + 1024, We2s + 1024, W0s + 1024, W1s + 1024, Wu1s + 6144,
      Wss + 2048, Wds + 2048, Wvs + 2048);
  mp_phase2<<<GP, 128>>>(Wu1s + 6144, Wu2s + 2048);

  // layer 2: buf0 -> buf1; reads slot0, writes slot1 (no hv for last layer)
  mp_phase1<false,false><<<GP, 128>>>(0, 0,
      We1s + 2048, We2s + 2048, W0s + 2048, W1s + 2048, Wu1s + 2*6144,
      Wss + 3072, Wds + 3072, Wvs + 3072);
  mp_phase2<<<GP, 128>>>(Wu1s + 2*6144, Wu2s + 2*2048);

  // layer 3 (LAST) fused with decode: reads buf1 + slot1
  mp_last_decode<<<GP, 128>>>(1,
      We1s + 3072, We2s + 3072, W0s + 3072,
      rrot, Wp0, Wt, bt,
      Wseq1, bseq1, Wseq2, bseq2, Wseq3, bseq3,
      lit_pos, Wchi, Wpsi, out);
}